// round 1
// baseline (speedup 1.0000x reference)
#include <cuda_runtime.h>
#include <cstddef>

// ---------------------------------------------------------------------------
// Problem constants (fixed by setup_inputs)
// ---------------------------------------------------------------------------
#define NPF 60000
#define NGW 300000
#define NSW 60000

// Scratch layout (floats)
static const size_t SZ_FEAT_GW = (size_t)NGW * 256;   // 76,800,000
static const size_t SZ_FEAT_PF = (size_t)NPF * 192;   // 11,520,000
static const size_t SZ_FEAT_SW = (size_t)NSW * 192;   // 11,520,000
static const size_t OFF_FEAT_GW = 0;
static const size_t OFF_FEAT_PF = OFF_FEAT_GW + SZ_FEAT_GW;
static const size_t OFF_FEAT_SW = OFF_FEAT_PF + SZ_FEAT_PF;
static const size_t OFF_H1      = OFF_FEAT_SW + SZ_FEAT_SW;       // h1_pf, h1_gw, h1_sw
static const size_t SZ_H1       = (size_t)(NPF + NGW + NSW) * 64; // 26,880,000
static const size_t OFF_CNT     = OFF_H1 + SZ_H1;
static const size_t SZ_CNT      = 3 * (size_t)NGW + 2 * (size_t)NPF + 2 * (size_t)NSW; // 1,140,000
static const size_t OFF_WCAT    = OFF_CNT + SZ_CNT;
static const size_t SZ_WCAT     = 64 * (128 + 96 + 96 + 256 + 192 + 192) + 6 * 64;     // 61,824

__device__ float g_scratch[127930000]; // ~512 MB static device scratch

// ---------------------------------------------------------------------------
// Kernels
// ---------------------------------------------------------------------------

__global__ void count_kernel(const int* __restrict__ ei_dst, int E, float* __restrict__ cnt) {
    int i = blockIdx.x * blockDim.x + threadIdx.x;
    if (i < E) atomicAdd(&cnt[ei_dst[i]], 1.0f);
}

__global__ void inv_kernel(float* __restrict__ cnt, int n) {
    int i = blockIdx.x * blockDim.x + threadIdx.x;
    if (i < n) {
        float c = cnt[i];
        cnt[i] = 1.0f / fmaxf(c, 1.0f);
    }
}

// Build concatenated weight matrix [64, K] where K = (nm+1)*Din:
//   cols [seg*Din, (seg+1)*Din) = Wl[m_seg]   for seg < nm
//   cols [nm*Din, K)            = Wl[self] + Wr[self] + sum_i Wr[m_i]
// bias[d] = b[self] + sum_i b[m_i]
__global__ void build_wcat(const float* __restrict__ Wl, const float* __restrict__ Wr,
                           const float* __restrict__ b, int Din,
                           int m0, int m1, int m2, int nm, int selfid,
                           float* __restrict__ wcat, float* __restrict__ bcat) {
    int K = (nm + 1) * Din;
    int idx = blockIdx.x * blockDim.x + threadIdx.x;
    if (idx >= 64 * K) return;
    int d = idx / K, c = idx % K;
    int seg = c / Din, k = c % Din;
    int ms[3] = {m0, m1, m2};
    int stride = 64 * Din;
    float v;
    if (seg < nm) {
        v = Wl[ms[seg] * stride + d * Din + k];
    } else {
        v = Wl[selfid * stride + d * Din + k] + Wr[selfid * stride + d * Din + k];
        for (int i = 0; i < nm; i++) v += Wr[ms[i] * stride + d * Din + k];
    }
    wcat[d * K + c] = v;
    if (c == 0) {
        float bb = b[selfid * 64 + d];
        for (int i = 0; i < nm; i++) bb += b[ms[i] * 64 + d];
        bcat[d] = bb;
    }
}

// Zero mean columns, copy x into the trailing Din columns.
__global__ void init_feat(const float* __restrict__ x, int Din,
                          float* __restrict__ feat, int K, int xoff, int N) {
    int idx = blockIdx.x * blockDim.x + threadIdx.x;
    if (idx >= N * K) return;
    int n = idx / K, c = idx % K;
    feat[idx] = (c >= xoff) ? x[n * Din + (c - xoff)] : 0.0f;
}

// Per-edge scatter of src row * inv_cnt[dst] into feat[dst, coloff : coloff+4G].
// G threads per edge, each handles one float4. Vectorized L2 reduction.
template <int G>
__global__ void aggregate(const int* __restrict__ ei, int E, const float* __restrict__ src,
                          float* __restrict__ feat, int K, int coloff,
                          const float* __restrict__ inv_cnt) {
    int t = blockIdx.x * blockDim.x + threadIdx.x;
    int e = t / G;
    int g = t % G;
    if (e >= E) return;
    int s = ei[e];
    int d = ei[E + e];
    const float4* srow = reinterpret_cast<const float4*>(src + (size_t)s * (G * 4));
    float4 v = srow[g];
    float sc = inv_cnt[d];
    float* dp = feat + (size_t)d * K + coloff + g * 4;
    asm volatile("red.global.add.v4.f32 [%0], {%1,%2,%3,%4};"
                 :: "l"(dp), "f"(v.x * sc), "f"(v.y * sc), "f"(v.z * sc), "f"(v.w * sc)
                 : "memory");
}

// out = relu(feat @ wcat.T + bcat)   (mode 0: write [N,64])
// mode 1: additionally fold final linear: out[n] = prelu(dot(h, linW) + linb)
// Block: 256 threads, 64 nodes x 64 dims tile, 4x4 per thread, K-chunks of 32.
__global__ void gemm_out(const float* __restrict__ feat, int N, int K,
                         const float* __restrict__ wcat, const float* __restrict__ bcat,
                         int mode, float* __restrict__ out,
                         const float* __restrict__ linW, const float* __restrict__ linb,
                         const float* __restrict__ pa) {
    __shared__ float sx[64 * 33];
    __shared__ float sw[64 * 33];
    int t = threadIdx.x;
    int tx = t & 15;        // dim group: dims tx*4 .. tx*4+3
    int ty = t >> 4;        // node group: nodes ty*4 .. ty*4+3
    int nbase = blockIdx.x * 64;

    float acc[4][4];
#pragma unroll
    for (int i = 0; i < 4; i++)
#pragma unroll
        for (int j = 0; j < 4; j++) acc[i][j] = bcat[tx * 4 + j];

    int nchunks = K >> 5;
    for (int c = 0; c < nchunks; c++) {
#pragma unroll
        for (int p = 0; p < 2; p++) {
            int r = (t >> 3) + p * 32;   // 0..63
            int col = (t & 7) * 4;       // 0..28
            int gr = nbase + r;
            float4 v = make_float4(0.f, 0.f, 0.f, 0.f);
            if (gr < N) v = *reinterpret_cast<const float4*>(feat + (size_t)gr * K + c * 32 + col);
            sx[r * 33 + col + 0] = v.x;
            sx[r * 33 + col + 1] = v.y;
            sx[r * 33 + col + 2] = v.z;
            sx[r * 33 + col + 3] = v.w;
            float4 w = *reinterpret_cast<const float4*>(wcat + (size_t)r * K + c * 32 + col);
            sw[r * 33 + col + 0] = w.x;
            sw[r * 33 + col + 1] = w.y;
            sw[r * 33 + col + 2] = w.z;
            sw[r * 33 + col + 3] = w.w;
        }
        __syncthreads();
#pragma unroll
        for (int k = 0; k < 32; k++) {
            float rx[4], rw[4];
#pragma unroll
            for (int i = 0; i < 4; i++) rx[i] = sx[(ty * 4 + i) * 33 + k];
#pragma unroll
            for (int j = 0; j < 4; j++) rw[j] = sw[(tx * 4 + j) * 33 + k];
#pragma unroll
            for (int i = 0; i < 4; i++)
#pragma unroll
                for (int j = 0; j < 4; j++) acc[i][j] += rx[i] * rw[j];
        }
        __syncthreads();
    }

    if (mode == 0) {
#pragma unroll
        for (int i = 0; i < 4; i++) {
            int n = nbase + ty * 4 + i;
            if (n < N) {
#pragma unroll
                for (int j = 0; j < 4; j++)
                    out[(size_t)n * 64 + tx * 4 + j] = fmaxf(acc[i][j], 0.0f);
            }
        }
    } else {
        float lw[4];
#pragma unroll
        for (int j = 0; j < 4; j++) lw[j] = linW[tx * 4 + j];
        float lb = linb[0];
        float a = pa[0];
#pragma unroll
        for (int i = 0; i < 4; i++) {
            float p = 0.f;
#pragma unroll
            for (int j = 0; j < 4; j++) p += fmaxf(acc[i][j], 0.0f) * lw[j];
#pragma unroll
            for (int off = 8; off >= 1; off >>= 1)
                p += __shfl_down_sync(0xffffffffu, p, off, 16);
            if (tx == 0) {
                int n = nbase + ty * 4 + i;
                if (n < N) {
                    float v = p + lb;
                    out[n] = (v >= 0.f) ? v : a * v;
                }
            }
        }
    }
}

// ---------------------------------------------------------------------------
// Launch
// ---------------------------------------------------------------------------
extern "C" void kernel_launch(void* const* d_in, const int* in_sizes, int n_in,
                              void* d_out, int out_size) {
    const float* x_pf = (const float*)d_in[0];
    const float* x_gw = (const float*)d_in[1];
    const float* x_sw = (const float*)d_in[2];
    const float* W1l  = (const float*)d_in[3];
    const float* b1l  = (const float*)d_in[4];
    const float* W1r  = (const float*)d_in[5];
    const float* W2l  = (const float*)d_in[6];
    const float* b2l  = (const float*)d_in[7];
    const float* W2r  = (const float*)d_in[8];
    const float* linW = (const float*)d_in[9];
    const float* linb = (const float*)d_in[10];
    const float* pa   = (const float*)d_in[11];
    const int* ei_pf_gw = (const int*)d_in[12];
    const int* ei_gw_pf = (const int*)d_in[13];
    const int* ei_pf_sw = (const int*)d_in[14];
    const int* ei_sw_pf = (const int*)d_in[15];
    const int* ei_sw_gw = (const int*)d_in[16];
    const int* ei_gw_sw = (const int*)d_in[17];
    const int* ei_gw_gw = (const int*)d_in[18];
    float* out = (float*)d_out;

    int E = in_sizes[12] / 2;

    float* scr;
    cudaGetSymbolAddress((void**)&scr, g_scratch);

    float* feat_gw = scr + OFF_FEAT_GW;
    float* feat_pf = scr + OFF_FEAT_PF;
    float* feat_sw = scr + OFF_FEAT_SW;
    float* h1_pf = scr + OFF_H1;
    float* h1_gw = h1_pf + (size_t)NPF * 64;
    float* h1_sw = h1_gw + (size_t)NGW * 64;

    float* cnt_base  = scr + OFF_CNT;
    float* cnt_pf_gw = cnt_base;                 // NGW
    float* cnt_sw_gw = cnt_pf_gw + NGW;          // NGW
    float* cnt_gw_gw = cnt_sw_gw + NGW;          // NGW
    float* cnt_gw_pf = cnt_gw_gw + NGW;          // NPF
    float* cnt_sw_pf = cnt_gw_pf + NPF;          // NPF
    float* cnt_pf_sw = cnt_sw_pf + NPF;          // NSW
    float* cnt_gw_sw = cnt_pf_sw + NSW;          // NSW

    float* wbase  = scr + OFF_WCAT;
    float* wL1_gw = wbase;             // 64*128
    float* wL1_pf = wL1_gw + 8192;     // 64*96
    float* wL1_sw = wL1_pf + 6144;     // 64*96
    float* wL2_gw = wL1_sw + 6144;     // 64*256
    float* wL2_pf = wL2_gw + 16384;    // 64*192
    float* wL2_sw = wL2_pf + 12288;    // 64*192
    float* bL1_gw = wL2_sw + 12288;
    float* bL1_pf = bL1_gw + 64;
    float* bL1_sw = bL1_pf + 64;
    float* bL2_gw = bL1_sw + 64;
    float* bL2_pf = bL2_gw + 64;
    float* bL2_sw = bL2_pf + 64;

    const int TB = 256;
    int eb = (E + TB - 1) / TB;

    // ---- degree counts -> inverse means scale ----
    cudaMemsetAsync(cnt_base, 0, SZ_CNT * sizeof(float), 0);
    count_kernel<<<eb, TB>>>(ei_pf_gw + E, E, cnt_pf_gw);
    count_kernel<<<eb, TB>>>(ei_sw_gw + E, E, cnt_sw_gw);
    count_kernel<<<eb, TB>>>(ei_gw_gw + E, E, cnt_gw_gw);
    count_kernel<<<eb, TB>>>(ei_gw_pf + E, E, cnt_gw_pf);
    count_kernel<<<eb, TB>>>(ei_sw_pf + E, E, cnt_sw_pf);
    count_kernel<<<eb, TB>>>(ei_pf_sw + E, E, cnt_pf_sw);
    count_kernel<<<eb, TB>>>(ei_gw_sw + E, E, cnt_gw_sw);
    inv_kernel<<<(int)((SZ_CNT + TB - 1) / TB), TB>>>(cnt_base, (int)SZ_CNT);

    // ---- combined weights ----
    build_wcat<<<(64 * 128 + TB - 1) / TB, TB>>>(W1l, W1r, b1l, 32, 0, 4, 6, 3, 7, wL1_gw, bL1_gw);
    build_wcat<<<(64 *  96 + TB - 1) / TB, TB>>>(W1l, W1r, b1l, 32, 1, 3, -1, 2, 9, wL1_pf, bL1_pf);
    build_wcat<<<(64 *  96 + TB - 1) / TB, TB>>>(W1l, W1r, b1l, 32, 2, 5, -1, 2, 8, wL1_sw, bL1_sw);
    build_wcat<<<(64 * 256 + TB - 1) / TB, TB>>>(W2l, W2r, b2l, 64, 0, 4, 6, 3, 7, wL2_gw, bL2_gw);
    build_wcat<<<(64 * 192 + TB - 1) / TB, TB>>>(W2l, W2r, b2l, 64, 1, 3, -1, 2, 9, wL2_pf, bL2_pf);
    build_wcat<<<(64 * 192 + TB - 1) / TB, TB>>>(W2l, W2r, b2l, 64, 2, 5, -1, 2, 8, wL2_sw, bL2_sw);

    // ---- layer 1 (Din = 32, G = 8) ----
    init_feat<<<(NGW * 128 + TB - 1) / TB, TB>>>(x_gw, 32, feat_gw, 128, 96, NGW);
    init_feat<<<(NPF *  96 + TB - 1) / TB, TB>>>(x_pf, 32, feat_pf, 96, 64, NPF);
    init_feat<<<(NSW *  96 + TB - 1) / TB, TB>>>(x_sw, 32, feat_sw, 96, 64, NSW);

    int ab8 = (E * 8 + TB - 1) / TB;
    aggregate<8><<<ab8, TB>>>(ei_pf_gw, E, x_pf, feat_gw, 128, 0,  cnt_pf_gw);
    aggregate<8><<<ab8, TB>>>(ei_sw_gw, E, x_sw, feat_gw, 128, 32, cnt_sw_gw);
    aggregate<8><<<ab8, TB>>>(ei_gw_gw, E, x_gw, feat_gw, 128, 64, cnt_gw_gw);
    aggregate<8><<<ab8, TB>>>(ei_gw_pf, E, x_gw, feat_pf, 96, 0,  cnt_gw_pf);
    aggregate<8><<<ab8, TB>>>(ei_sw_pf, E, x_sw, feat_pf, 96, 32, cnt_sw_pf);
    aggregate<8><<<ab8, TB>>>(ei_pf_sw, E, x_pf, feat_sw, 96, 0,  cnt_pf_sw);
    aggregate<8><<<ab8, TB>>>(ei_gw_sw, E, x_gw, feat_sw, 96, 32, cnt_gw_sw);

    gemm_out<<<(NGW + 63) / 64, TB>>>(feat_gw, NGW, 128, wL1_gw, bL1_gw, 0, h1_gw, nullptr, nullptr, nullptr);
    gemm_out<<<(NPF + 63) / 64, TB>>>(feat_pf, NPF,  96, wL1_pf, bL1_pf, 0, h1_pf, nullptr, nullptr, nullptr);
    gemm_out<<<(NSW + 63) / 64, TB>>>(feat_sw, NSW,  96, wL1_sw, bL1_sw, 0, h1_sw, nullptr, nullptr, nullptr);

    // ---- layer 2 (Din = 64, G = 16) ----
    init_feat<<<(NGW * 256 + TB - 1) / TB, TB>>>(h1_gw, 64, feat_gw, 256, 192, NGW);
    init_feat<<<(NPF * 192 + TB - 1) / TB, TB>>>(h1_pf, 64, feat_pf, 192, 128, NPF);
    init_feat<<<(NSW * 192 + TB - 1) / TB, TB>>>(h1_sw, 64, feat_sw, 192, 128, NSW);

    int ab16 = (E * 16 + TB - 1) / TB;
    aggregate<16><<<ab16, TB>>>(ei_pf_gw, E, h1_pf, feat_gw, 256, 0,   cnt_pf_gw);
    aggregate<16><<<ab16, TB>>>(ei_sw_gw, E, h1_sw, feat_gw, 256, 64,  cnt_sw_gw);
    aggregate<16><<<ab16, TB>>>(ei_gw_gw, E, h1_gw, feat_gw, 256, 128, cnt_gw_gw);
    aggregate<16><<<ab16, TB>>>(ei_gw_pf, E, h1_gw, feat_pf, 192, 0,   cnt_gw_pf);
    aggregate<16><<<ab16, TB>>>(ei_sw_pf, E, h1_sw, feat_pf, 192, 64,  cnt_sw_pf);
    aggregate<16><<<ab16, TB>>>(ei_pf_sw, E, h1_pf, feat_sw, 192, 0,   cnt_pf_sw);
    aggregate<16><<<ab16, TB>>>(ei_gw_sw, E, h1_gw, feat_sw, 192, 64,  cnt_gw_sw);

    // out layout: out_gw [300000], out_sw [60000], h_pf [60000*64]
    gemm_out<<<(NGW + 63) / 64, TB>>>(feat_gw, NGW, 256, wL2_gw, bL2_gw, 1, out,           linW, linb, pa);
    gemm_out<<<(NSW + 63) / 64, TB>>>(feat_sw, NSW, 192, wL2_sw, bL2_sw, 1, out + NGW,     linW, linb, pa);
    gemm_out<<<(NPF + 63) / 64, TB>>>(feat_pf, NPF, 192, wL2_pf, bL2_pf, 0, out + NGW + NSW, nullptr, nullptr, nullptr);
}

// round 2
// speedup vs baseline: 1.1633x; 1.1633x over previous
#include <cuda_runtime.h>
#include <cstddef>
#include <cstdint>

#define NPF 60000
#define NGW 300000
#define NSW 60000

// ---------------- scratch layout (4-byte units) ----------------
static const size_t OFF_FEAT_GW = 0;                         // 76,800,000 (NGW*256)
static const size_t OFF_FEAT_PF = 76800000;                  // 11,520,000 (NPF*192)
static const size_t OFF_FEAT_SW = 88320000;                  // 11,520,000
static const size_t OFF_H1      = 99840000;                  // 26,880,000
static const size_t OFF_CNT     = 126720000;                 // 1,140,000
static const size_t OFF_FILL    = 127860000;                 // 1,140,000
static const size_t OFF_ROWPTR  = 129000000;                 // 1,140,007
static const size_t OFF_COLIDX  = 130140016;                 // 7,000,000
static const size_t OFF_INCL    = 137140016;                 // 300,000
static const size_t OFF_BSUMS   = 137440016;                 // 1,024
static const size_t OFF_WCAT    = 137441040;                 // ~62,000

__device__ float g_scratch[137600000];   // ~550 MB

// ---------------- CSR build ----------------
__global__ void count_edges(const int* __restrict__ ei, int E, int* __restrict__ cnt) {
    int i = blockIdx.x * blockDim.x + threadIdx.x;
    if (i < E) atomicAdd(&cnt[ei[E + i]], 1);
}

__global__ void scan_partial(const int* __restrict__ cnt, int n,
                             int* __restrict__ incl, int* __restrict__ bsums) {
    __shared__ int s[1024];
    int tid = threadIdx.x;
    int i = blockIdx.x * 1024 + tid;
    int v = (i < n) ? cnt[i] : 0;
    s[tid] = v; __syncthreads();
#pragma unroll
    for (int off = 1; off < 1024; off <<= 1) {
        int t2 = (tid >= off) ? s[tid - off] : 0;
        __syncthreads();
        s[tid] += t2;
        __syncthreads();
    }
    if (i < n) incl[i] = s[tid];
    if (tid == 1023) bsums[blockIdx.x] = s[1023];
}

__global__ void scan_bsums(int* __restrict__ bs, int nb) {
    __shared__ int s[1024];
    int tid = threadIdx.x;
    int v = (tid < nb) ? bs[tid] : 0;
    s[tid] = v; __syncthreads();
#pragma unroll
    for (int off = 1; off < 1024; off <<= 1) {
        int t2 = (tid >= off) ? s[tid - off] : 0;
        __syncthreads();
        s[tid] += t2;
        __syncthreads();
    }
    if (tid < nb) bs[tid] = s[tid] - v;   // exclusive
}

__global__ void scan_final(const int* __restrict__ incl, const int* __restrict__ bs,
                           int n, int* __restrict__ rowptr) {
    int i = blockIdx.x * blockDim.x + threadIdx.x;
    if (i < n) rowptr[i + 1] = incl[i] + bs[i >> 10];
    if (i == 0) rowptr[0] = 0;
}

__global__ void scatter_edges(const int* __restrict__ ei, int E,
                              const int* __restrict__ rowptr, int* __restrict__ fill,
                              int* __restrict__ colidx) {
    int i = blockIdx.x * blockDim.x + threadIdx.x;
    if (i < E) {
        int s = ei[i];
        int d = ei[E + i];
        int pos = rowptr[d] + atomicAdd(&fill[d], 1);
        colidx[pos] = s;
    }
}

// ---------------- combined weights ----------------
__global__ void build_wcat(const float* __restrict__ Wl, const float* __restrict__ Wr,
                           const float* __restrict__ b, int Din,
                           int m0, int m1, int m2, int nm, int selfid,
                           float* __restrict__ wcat, float* __restrict__ bcat) {
    int K = (nm + 1) * Din;
    int idx = blockIdx.x * blockDim.x + threadIdx.x;
    if (idx >= 64 * K) return;
    int d = idx / K, c = idx % K;
    int seg = c / Din, k = c % Din;
    int ms[3] = {m0, m1, m2};
    int stride = 64 * Din;
    float v;
    if (seg < nm) {
        v = Wl[ms[seg] * stride + d * Din + k];
    } else {
        v = Wl[selfid * stride + d * Din + k] + Wr[selfid * stride + d * Din + k];
        for (int i = 0; i < nm; i++) v += Wr[ms[i] * stride + d * Din + k];
    }
    wcat[d * K + c] = v;
    if (c == 0) {
        float bb = b[selfid * 64 + d];
        for (int i = 0; i < nm; i++) bb += b[ms[i] * 64 + d];
        bcat[d] = bb;
    }
}

// ---------------- CSR gather: feat[n] = [mean_seg0 | mean_seg1 (| mean_seg2) | x_self] --------
template <int G, int NSEG>
__global__ void gather(const int* __restrict__ rp0, const int* __restrict__ ci0,
                       const float* __restrict__ s0,
                       const int* __restrict__ rp1, const int* __restrict__ ci1,
                       const float* __restrict__ s1,
                       const int* __restrict__ rp2, const int* __restrict__ ci2,
                       const float* __restrict__ s2,
                       const float* __restrict__ xself,
                       float* __restrict__ feat, int K, int N) {
    const int Din = G * 4;
    int t = blockIdx.x * blockDim.x + threadIdx.x;
    int node = t / G;
    int g = t % G;
    if (node >= N) return;
    float* frow = feat + (size_t)node * K;

    const int* rps[3] = {rp0, rp1, rp2};
    const int* cis[3] = {ci0, ci1, ci2};
    const float* ss[3] = {s0, s1, s2};
#pragma unroll
    for (int seg = 0; seg < NSEG; seg++) {
        int beg = rps[seg][node];
        int end = rps[seg][node + 1];
        float4 acc = make_float4(0.f, 0.f, 0.f, 0.f);
        for (int e = beg; e < end; e++) {
            int sidx = cis[seg][e];
            float4 v = *reinterpret_cast<const float4*>(ss[seg] + (size_t)sidx * Din + g * 4);
            acc.x += v.x; acc.y += v.y; acc.z += v.z; acc.w += v.w;
        }
        int deg = end - beg;
        float inv = (deg > 0) ? (1.0f / (float)deg) : 1.0f;
        acc.x *= inv; acc.y *= inv; acc.z *= inv; acc.w *= inv;
        *reinterpret_cast<float4*>(frow + seg * Din + g * 4) = acc;
    }
    float4 xs = *reinterpret_cast<const float4*>(xself + (size_t)node * Din + g * 4);
    *reinterpret_cast<float4*>(frow + NSEG * Din + g * 4) = xs;
}

// ---------------- tf32 tensor-core GEMM ----------------
// out = relu(feat[N,K] @ wcat[64,K]^T + bcat)  (mode 0: write [N,64])
// mode 1: out[n] = prelu(dot(relu(h[n]), linW) + linb)
#define BM 128
#define BN 64
#define BK 32

__device__ __forceinline__ float to_tf32(float x) {
    float r;
    asm("cvt.rna.tf32.f32 %0, %1;" : "=f"(r) : "f"(x));
    return r;
}

__device__ __forceinline__ void mma_tf32(float& d0, float& d1, float& d2, float& d3,
                                         uint32_t a0, uint32_t a1, uint32_t a2, uint32_t a3,
                                         uint32_t b0, uint32_t b1) {
    asm volatile("mma.sync.aligned.m16n8k8.row.col.f32.tf32.tf32.f32 "
                 "{%0,%1,%2,%3}, {%4,%5,%6,%7}, {%8,%9}, {%0,%1,%2,%3};"
                 : "+f"(d0), "+f"(d1), "+f"(d2), "+f"(d3)
                 : "r"(a0), "r"(a1), "r"(a2), "r"(a3), "r"(b0), "r"(b1));
}

__global__ void __launch_bounds__(256) gemm_tc(
        const float* __restrict__ feat, int N, int K,
        const float* __restrict__ wcat, const float* __restrict__ bcat,
        int mode, float* __restrict__ out,
        const float* __restrict__ linW, const float* __restrict__ linb,
        const float* __restrict__ pa) {
    __shared__ float sA[BK * 136];   // [k][m], m-stride 136
    __shared__ float sB[BK * 72];    // [k][n], n-stride 72
    __shared__ float sred[BM];

    int tid = threadIdx.x;
    int warp = tid >> 5, lane = tid & 31;
    int wm = warp >> 1;              // 0..3 (m)
    int wn = warp & 1;               // 0..1 (n)
    int r = lane >> 2, c = lane & 3;
    int nbase = blockIdx.x * BM;

    float acc[2][4][4];
#pragma unroll
    for (int mi = 0; mi < 2; mi++)
#pragma unroll
        for (int ni = 0; ni < 4; ni++) {
            int col0 = wn * 32 + ni * 8 + 2 * c;
            acc[mi][ni][0] = acc[mi][ni][2] = bcat[col0];
            acc[mi][ni][1] = acc[mi][ni][3] = bcat[col0 + 1];
        }

    int arow = tid & 127;
    int akb  = (tid >> 7) * 16;
    int brow = tid & 63;
    int bkb  = (tid >> 6) * 8;
    bool avalid = (nbase + arow) < N;
    const float* arow_ptr = feat + (size_t)(avalid ? (nbase + arow) : 0) * K;
    const float* brow_ptr = wcat + (size_t)brow * K;

    for (int c0 = 0; c0 < K; c0 += BK) {
#pragma unroll
        for (int j = 0; j < 4; j++) {
            float4 v = make_float4(0.f, 0.f, 0.f, 0.f);
            if (avalid) v = *reinterpret_cast<const float4*>(arow_ptr + c0 + akb + j * 4);
            sA[(akb + j * 4 + 0) * 136 + arow] = to_tf32(v.x);
            sA[(akb + j * 4 + 1) * 136 + arow] = to_tf32(v.y);
            sA[(akb + j * 4 + 2) * 136 + arow] = to_tf32(v.z);
            sA[(akb + j * 4 + 3) * 136 + arow] = to_tf32(v.w);
        }
#pragma unroll
        for (int j = 0; j < 2; j++) {
            float4 w = *reinterpret_cast<const float4*>(brow_ptr + c0 + bkb + j * 4);
            sB[(bkb + j * 4 + 0) * 72 + brow] = to_tf32(w.x);
            sB[(bkb + j * 4 + 1) * 72 + brow] = to_tf32(w.y);
            sB[(bkb + j * 4 + 2) * 72 + brow] = to_tf32(w.z);
            sB[(bkb + j * 4 + 3) * 72 + brow] = to_tf32(w.w);
        }
        __syncthreads();
#pragma unroll
        for (int ks = 0; ks < 4; ks++) {
            int k0 = ks * 8;
            uint32_t bf[4][2];
#pragma unroll
            for (int ni = 0; ni < 4; ni++) {
                int nb = wn * 32 + ni * 8;
                bf[ni][0] = __float_as_uint(sB[(k0 + c) * 72 + nb + r]);
                bf[ni][1] = __float_as_uint(sB[(k0 + c + 4) * 72 + nb + r]);
            }
#pragma unroll
            for (int mi = 0; mi < 2; mi++) {
                int mb = wm * 32 + mi * 16;
                uint32_t a0 = __float_as_uint(sA[(k0 + c) * 136 + mb + r]);
                uint32_t a1 = __float_as_uint(sA[(k0 + c) * 136 + mb + r + 8]);
                uint32_t a2 = __float_as_uint(sA[(k0 + c + 4) * 136 + mb + r]);
                uint32_t a3 = __float_as_uint(sA[(k0 + c + 4) * 136 + mb + r + 8]);
#pragma unroll
                for (int ni = 0; ni < 4; ni++)
                    mma_tf32(acc[mi][ni][0], acc[mi][ni][1], acc[mi][ni][2], acc[mi][ni][3],
                             a0, a1, a2, a3, bf[ni][0], bf[ni][1]);
            }
        }
        __syncthreads();
    }

    if (mode == 0) {
#pragma unroll
        for (int mi = 0; mi < 2; mi++) {
            int m0 = nbase + wm * 32 + mi * 16 + r;
#pragma unroll
            for (int ni = 0; ni < 4; ni++) {
                int col = wn * 32 + ni * 8 + 2 * c;
                if (m0 < N) {
                    float2 v = make_float2(fmaxf(acc[mi][ni][0], 0.f), fmaxf(acc[mi][ni][1], 0.f));
                    *reinterpret_cast<float2*>(out + (size_t)m0 * 64 + col) = v;
                }
                if (m0 + 8 < N) {
                    float2 v = make_float2(fmaxf(acc[mi][ni][2], 0.f), fmaxf(acc[mi][ni][3], 0.f));
                    *reinterpret_cast<float2*>(out + (size_t)(m0 + 8) * 64 + col) = v;
                }
            }
        }
    } else {
        float lb = linb[0];
        float a = pa[0];
        float pl[2], ph[2];
#pragma unroll
        for (int mi = 0; mi < 2; mi++) {
            pl[mi] = 0.f; ph[mi] = 0.f;
#pragma unroll
            for (int ni = 0; ni < 4; ni++) {
                int col = wn * 32 + ni * 8 + 2 * c;
                float w0 = linW[col], w1 = linW[col + 1];
                pl[mi] += fmaxf(acc[mi][ni][0], 0.f) * w0 + fmaxf(acc[mi][ni][1], 0.f) * w1;
                ph[mi] += fmaxf(acc[mi][ni][2], 0.f) * w0 + fmaxf(acc[mi][ni][3], 0.f) * w1;
            }
            pl[mi] += __shfl_xor_sync(0xffffffffu, pl[mi], 1);
            pl[mi] += __shfl_xor_sync(0xffffffffu, pl[mi], 2);
            ph[mi] += __shfl_xor_sync(0xffffffffu, ph[mi], 1);
            ph[mi] += __shfl_xor_sync(0xffffffffu, ph[mi], 2);
        }
        if (wn == 0 && c == 0) {
#pragma unroll
            for (int mi = 0; mi < 2; mi++) {
                sred[wm * 32 + mi * 16 + r] = pl[mi];
                sred[wm * 32 + mi * 16 + r + 8] = ph[mi];
            }
        }
        __syncthreads();
        if (wn == 1 && c == 0) {
#pragma unroll
            for (int mi = 0; mi < 2; mi++) {
                int rl = wm * 32 + mi * 16 + r;
                int nl = nbase + rl;
                if (nl < N) {
                    float v = pl[mi] + sred[rl] + lb;
                    out[nl] = (v >= 0.f) ? v : a * v;
                }
                int nh = nl + 8;
                if (nh < N) {
                    float v = ph[mi] + sred[rl + 8] + lb;
                    out[nh] = (v >= 0.f) ? v : a * v;
                }
            }
        }
    }
}

// ---------------- launch ----------------
extern "C" void kernel_launch(void* const* d_in, const int* in_sizes, int n_in,
                              void* d_out, int out_size) {
    const float* x_pf = (const float*)d_in[0];
    const float* x_gw = (const float*)d_in[1];
    const float* x_sw = (const float*)d_in[2];
    const float* W1l  = (const float*)d_in[3];
    const float* b1l  = (const float*)d_in[4];
    const float* W1r  = (const float*)d_in[5];
    const float* W2l  = (const float*)d_in[6];
    const float* b2l  = (const float*)d_in[7];
    const float* W2r  = (const float*)d_in[8];
    const float* linW = (const float*)d_in[9];
    const float* linb = (const float*)d_in[10];
    const float* pa   = (const float*)d_in[11];
    const int* eis[7] = {
        (const int*)d_in[12],  // pf_gw
        (const int*)d_in[16],  // sw_gw
        (const int*)d_in[18],  // gw_gw
        (const int*)d_in[13],  // gw_pf
        (const int*)d_in[15],  // sw_pf
        (const int*)d_in[14],  // pf_sw
        (const int*)d_in[17],  // gw_sw
    };
    float* out = (float*)d_out;
    int E = in_sizes[12] / 2;

    float* scr;
    cudaGetSymbolAddress((void**)&scr, g_scratch);

    float* feat_gw = scr + OFF_FEAT_GW;
    float* feat_pf = scr + OFF_FEAT_PF;
    float* feat_sw = scr + OFF_FEAT_SW;
    float* h1_pf = scr + OFF_H1;
    float* h1_gw = h1_pf + (size_t)NPF * 64;
    float* h1_sw = h1_gw + (size_t)NGW * 64;

    int* cnt_base    = (int*)(scr + OFF_CNT);
    int* fill_base   = (int*)(scr + OFF_FILL);
    int* rowptr_base = (int*)(scr + OFF_ROWPTR);
    int* colidx_base = (int*)(scr + OFF_COLIDX);
    int* incl        = (int*)(scr + OFF_INCL);
    int* bsums       = (int*)(scr + OFF_BSUMS);

    int ns[7] = {NGW, NGW, NGW, NPF, NPF, NSW, NSW};
    int* cnts[7]; int* rps[7]; int* fills[7]; int* cols[7];
    {
        size_t coff = 0, roff = 0;
        for (int t = 0; t < 7; t++) {
            cnts[t]  = cnt_base + coff;
            fills[t] = fill_base + coff;
            rps[t]   = rowptr_base + roff;
            cols[t]  = colidx_base + (size_t)t * E;
            coff += ns[t];
            roff += ns[t] + 1;
        }
    }

    float* wbase  = scr + OFF_WCAT;
    float* wL1_gw = wbase;
    float* wL1_pf = wL1_gw + 8192;
    float* wL1_sw = wL1_pf + 6144;
    float* wL2_gw = wL1_sw + 6144;
    float* wL2_pf = wL2_gw + 16384;
    float* wL2_sw = wL2_pf + 12288;
    float* bL1_gw = wL2_sw + 12288;
    float* bL1_pf = bL1_gw + 64;
    float* bL1_sw = bL1_pf + 64;
    float* bL2_gw = bL1_sw + 64;
    float* bL2_pf = bL2_gw + 64;
    float* bL2_sw = bL2_pf + 64;

    const int TB = 256;
    int eb = (E + TB - 1) / TB;

    // ---- CSR build (7 edge types) ----
    cudaMemsetAsync(cnt_base, 0, 1140000 * sizeof(int), 0);
    cudaMemsetAsync(fill_base, 0, 1140000 * sizeof(int), 0);
    for (int t = 0; t < 7; t++)
        count_edges<<<eb, TB>>>(eis[t], E, cnts[t]);
    for (int t = 0; t < 7; t++) {
        int n = ns[t];
        int nb = (n + 1023) / 1024;
        scan_partial<<<nb, 1024>>>(cnts[t], n, incl, bsums);
        scan_bsums<<<1, 1024>>>(bsums, nb);
        scan_final<<<(n + TB - 1) / TB, TB>>>(incl, bsums, n, rps[t]);
        scatter_edges<<<eb, TB>>>(eis[t], E, rps[t], fills[t], cols[t]);
    }

    // ---- combined weights ----
    build_wcat<<<(64 * 128 + TB - 1) / TB, TB>>>(W1l, W1r, b1l, 32, 0, 4, 6, 3, 7, wL1_gw, bL1_gw);
    build_wcat<<<(64 *  96 + TB - 1) / TB, TB>>>(W1l, W1r, b1l, 32, 1, 3, -1, 2, 9, wL1_pf, bL1_pf);
    build_wcat<<<(64 *  96 + TB - 1) / TB, TB>>>(W1l, W1r, b1l, 32, 2, 5, -1, 2, 8, wL1_sw, bL1_sw);
    build_wcat<<<(64 * 256 + TB - 1) / TB, TB>>>(W2l, W2r, b2l, 64, 0, 4, 6, 3, 7, wL2_gw, bL2_gw);
    build_wcat<<<(64 * 192 + TB - 1) / TB, TB>>>(W2l, W2r, b2l, 64, 1, 3, -1, 2, 9, wL2_pf, bL2_pf);
    build_wcat<<<(64 * 192 + TB - 1) / TB, TB>>>(W2l, W2r, b2l, 64, 2, 5, -1, 2, 8, wL2_sw, bL2_sw);

    // ---- layer 1: gather (G=8, Din=32) + GEMM ----
    gather<8, 3><<<((size_t)NGW * 8 + TB - 1) / TB, TB>>>(
        rps[0], cols[0], x_pf, rps[1], cols[1], x_sw, rps[2], cols[2], x_gw,
        x_gw, feat_gw, 128, NGW);
    gather<8, 2><<<((size_t)NPF * 8 + TB - 1) / TB, TB>>>(
        rps[3], cols[3], x_gw, rps[4], cols[4], x_sw, nullptr, nullptr, nullptr,
        x_pf, feat_pf, 96, NPF);
    gather<8, 2><<<((size_t)NSW * 8 + TB - 1) / TB, TB>>>(
        rps[5], cols[5], x_pf, rps[6], cols[6], x_gw, nullptr, nullptr, nullptr,
        x_sw, feat_sw, 96, NSW);

    gemm_tc<<<(NGW + BM - 1) / BM, 256>>>(feat_gw, NGW, 128, wL1_gw, bL1_gw, 0, h1_gw, nullptr, nullptr, nullptr);
    gemm_tc<<<(NPF + BM - 1) / BM, 256>>>(feat_pf, NPF,  96, wL1_pf, bL1_pf, 0, h1_pf, nullptr, nullptr, nullptr);
    gemm_tc<<<(NSW + BM - 1) / BM, 256>>>(feat_sw, NSW,  96, wL1_sw, bL1_sw, 0, h1_sw, nullptr, nullptr, nullptr);

    // ---- layer 2: gather (G=16, Din=64) + GEMM ----
    gather<16, 3><<<((size_t)NGW * 16 + TB - 1) / TB, TB>>>(
        rps[0], cols[0], h1_pf, rps[1], cols[1], h1_sw, rps[2], cols[2], h1_gw,
        h1_gw, feat_gw, 256, NGW);
    gather<16, 2><<<((size_t)NPF * 16 + TB - 1) / TB, TB>>>(
        rps[3], cols[3], h1_gw, rps[4], cols[4], h1_sw, nullptr, nullptr, nullptr,
        h1_pf, feat_pf, 192, NPF);
    gather<16, 2><<<((size_t)NSW * 16 + TB - 1) / TB, TB>>>(
        rps[5], cols[5], h1_pf, rps[6], cols[6], h1_gw, nullptr, nullptr, nullptr,
        h1_sw, feat_sw, 192, NSW);

    // out layout: out_gw [NGW], out_sw [NSW], h_pf [NPF*64]
    gemm_tc<<<(NGW + BM - 1) / BM, 256>>>(feat_gw, NGW, 256, wL2_gw, bL2_gw, 1, out,       linW, linb, pa);
    gemm_tc<<<(NSW + BM - 1) / BM, 256>>>(feat_sw, NSW, 192, wL2_sw, bL2_sw, 1, out + NGW, linW, linb, pa);
    gemm_tc<<<(NPF + BM - 1) / BM, 256>>>(feat_pf, NPF, 192, wL2_pf, bL2_pf, 0, out + NGW + NSW, nullptr, nullptr, nullptr);
}

// round 8
// speedup vs baseline: 1.5425x; 1.3260x over previous
#include <cuda_runtime.h>
#include <cstddef>
#include <cstdint>

#define NPF 60000
#define NGW 300000
#define NSW 60000
#define EMAX 1000000

// ---------------- scratch layout (4-byte units, ALL multiples of 4 for 16B alignment) ----
static const size_t OFF_H1     = 0;           // 26,880,000 floats
static const size_t OFF_CNT    = 26880000;    // padded per-type regions (1,163,264)
static const size_t OFF_FILL   = 28043264;
static const size_t OFF_INCL   = 29206528;
static const size_t OFF_BSUMS  = 30369792;    // 7*512
static const size_t OFF_ROWPTR = 30373376;    // 1,140,007 used, padded to 1,140,008
static const size_t OFF_COLIDX = 31513384;    // 7,000,000
static const size_t OFF_WCAT   = 38513384;    // ~62,000  (16B aligned)

__device__ float g_scratch[38600000];   // ~155 MB

// types: 0 pf_gw, 1 sw_gw, 2 gw_gw, 3 gw_pf, 4 sw_pf, 5 pf_sw, 6 gw_sw
struct ScanCfg { int ps[7]; int nblk[7]; int n[7]; int rpo[7]; };
struct Ptrs7i { const int* p[7]; };
struct Ptrs7o { int* p[7]; };

// ---------------- CSR build (batched) ----------------
__global__ void count_all(Ptrs7i ei, Ptrs7o cnt, int E) {
    int t = blockIdx.y;
    int i = blockIdx.x * blockDim.x + threadIdx.x;
    if (i < E) atomicAdd(&cnt.p[t][ei.p[t][E + i]], 1);
}

__global__ void scan_partial(const int* __restrict__ cnt, int* __restrict__ incl,
                             int* __restrict__ bsums, ScanCfg sc) {
    int t = blockIdx.y;
    if ((int)blockIdx.x >= sc.nblk[t]) return;
    __shared__ int s[1024];
    int tid = threadIdx.x;
    int base = sc.ps[t] + blockIdx.x * 1024;
    int v = cnt[base + tid];
    s[tid] = v; __syncthreads();
#pragma unroll
    for (int off = 1; off < 1024; off <<= 1) {
        int t2 = (tid >= off) ? s[tid - off] : 0;
        __syncthreads();
        s[tid] += t2;
        __syncthreads();
    }
    incl[base + tid] = s[tid];
    if (tid == 1023) bsums[t * 512 + blockIdx.x] = s[1023];
}

__global__ void scan_bsums(int* __restrict__ bs, ScanCfg sc) {
    int t = blockIdx.y;
    int nb = sc.nblk[t];
    __shared__ int s[512];
    int tid = threadIdx.x;
    int v = (tid < nb) ? bs[t * 512 + tid] : 0;
    s[tid] = v; __syncthreads();
#pragma unroll
    for (int off = 1; off < 512; off <<= 1) {
        int t2 = (tid >= off) ? s[tid - off] : 0;
        __syncthreads();
        s[tid] += t2;
        __syncthreads();
    }
    if (tid < nb) bs[t * 512 + tid] = s[tid] - v;   // exclusive
}

__global__ void scan_final(const int* __restrict__ incl, const int* __restrict__ bs,
                           int* __restrict__ rowptr, ScanCfg sc) {
    int t = blockIdx.y;
    int i = blockIdx.x * blockDim.x + threadIdx.x;
    int n = sc.n[t];
    if (i < n) rowptr[sc.rpo[t] + i + 1] = incl[sc.ps[t] + i] + bs[t * 512 + (i >> 10)];
    if (i == 0) rowptr[sc.rpo[t]] = 0;
}

__global__ void scatter_all(Ptrs7i ei, Ptrs7i rp, Ptrs7o fill, Ptrs7o col, int E) {
    int t = blockIdx.y;
    int i = blockIdx.x * blockDim.x + threadIdx.x;
    if (i < E) {
        int s = ei.p[t][i];
        int d = ei.p[t][E + i];
        int pos = rp.p[t][d] + atomicAdd(&fill.p[t][d], 1);
        col.p[t][pos] = s;
    }
}

// ---------------- combined weights (batched) ----------------
struct WCfg {
    const float* Wl; const float* Wr; const float* b;
    float* w; float* bc;
    int Din, nm, selfid, m0, m1, m2;
};
struct WAll { WCfg c[6]; };

__global__ void build_wcat_all(WAll wa) {
    WCfg cf = wa.c[blockIdx.y];
    int K = (cf.nm + 1) * cf.Din;
    int idx = blockIdx.x * blockDim.x + threadIdx.x;
    if (idx >= 64 * K) return;
    int d = idx / K, c = idx % K;
    int seg = c / cf.Din, k = c % cf.Din;
    int ms[3] = {cf.m0, cf.m1, cf.m2};
    int stride = 64 * cf.Din;
    float v;
    if (seg < cf.nm) {
        v = cf.Wl[ms[seg] * stride + d * cf.Din + k];
    } else {
        v = cf.Wl[cf.selfid * stride + d * cf.Din + k] + cf.Wr[cf.selfid * stride + d * cf.Din + k];
        for (int i = 0; i < cf.nm; i++) v += cf.Wr[ms[i] * stride + d * cf.Din + k];
    }
    cf.w[d * K + c] = v;
    if (c == 0) {
        float bb = cf.b[cf.selfid * 64 + d];
        for (int i = 0; i < cf.nm; i++) bb += cf.b[ms[i] * 64 + d];
        cf.bc[d] = bb;
    }
}

// ---------------- fused gather + tf32 GEMM (segment-streamed) ----------------
__device__ __forceinline__ float to_tf32(float x) {
    float r;
    asm("cvt.rna.tf32.f32 %0, %1;" : "=f"(r) : "f"(x));
    return r;
}

__device__ __forceinline__ void mma_tf32(float& d0, float& d1, float& d2, float& d3,
                                         uint32_t a0, uint32_t a1, uint32_t a2, uint32_t a3,
                                         uint32_t b0, uint32_t b1) {
    asm volatile("mma.sync.aligned.m16n8k8.row.col.f32.tf32.tf32.f32 "
                 "{%0,%1,%2,%3}, {%4,%5,%6,%7}, {%8,%9}, {%0,%1,%2,%3};"
                 : "+f"(d0), "+f"(d1), "+f"(d2), "+f"(d3)
                 : "r"(a0), "r"(a1), "r"(a2), "r"(a3), "r"(b0), "r"(b1));
}

// Per block: 128 dst nodes. For each K-segment (edge-type mean, or self row):
//   stage 64xDIN weight slice + gather 128xDIN A slice into smem, mma, accumulate.
// Small smem (<=54KB) -> multiple CTAs/SM for gather latency hiding.
// mode 0: out[n*64+col] = relu(h);  mode 1: out[n] = prelu(dot(relu(h), linW)+linb)
template <int DIN, int NSEG>
__global__ void __launch_bounds__(512, 2) fused_layer(
        const int* __restrict__ rp0, const int* __restrict__ ci0, const float* __restrict__ s0,
        const int* __restrict__ rp1, const int* __restrict__ ci1, const float* __restrict__ s1,
        const int* __restrict__ rp2, const int* __restrict__ ci2, const float* __restrict__ s2,
        const float* __restrict__ xself, int N,
        const float* __restrict__ wcat, const float* __restrict__ bcat,
        int mode, float* __restrict__ out,
        const float* __restrict__ linW, const float* __restrict__ linb,
        const float* __restrict__ pa) {
    constexpr int K = (NSEG + 1) * DIN;   // wcat row stride
    constexpr int S2 = DIN + 4;           // smem row stride (16B-aligned, conflict-staggered)
    constexpr int G = DIN / 4;            // float4 chunks per row
    constexpr int NPI = 512 / G;          // nodes gathered per iteration
    constexpr int NIT = 128 / NPI;
    constexpr int C4 = DIN / 4;           // float4 per B row
    constexpr int BL = (64 * C4) / 512;   // B float4 loads per thread (1 or 2)

    __shared__ float sA[128 * S2];
    __shared__ float sB[64 * S2];
    __shared__ float sred[512];

    int tid = threadIdx.x;
    int nbase = blockIdx.x * 128;
    int warp = tid >> 5, lane = tid & 31;
    int wm = warp >> 2, wn = warp & 3;
    int r = lane >> 2, c = lane & 3;

    float acc[2][2][4];
#pragma unroll
    for (int mi = 0; mi < 2; mi++)
#pragma unroll
        for (int ni = 0; ni < 2; ni++) {
            int col = wn * 16 + ni * 8 + 2 * c;
            acc[mi][ni][0] = acc[mi][ni][2] = bcat[col];
            acc[mi][ni][1] = acc[mi][ni][3] = bcat[col + 1];
        }

    const int* rps[3] = {rp0, rp1, rp2};
    const int* cis[3] = {ci0, ci1, ci2};
    const float* ss[3] = {s0, s1, s2};
    int g = tid & (G - 1);
    int nl0 = tid / G;

#pragma unroll
    for (int seg = 0; seg <= NSEG; seg++) {
        // ---- stage weight slice [64][DIN] ----
#pragma unroll
        for (int j = 0; j < BL; j++) {
            int idx = j * 512 + tid;
            int row = idx / C4, cc = idx % C4;
            float4 w = *reinterpret_cast<const float4*>(wcat + (size_t)row * K + seg * DIN + cc * 4);
            float* bp = sB + row * S2 + cc * 4;
            bp[0] = to_tf32(w.x); bp[1] = to_tf32(w.y); bp[2] = to_tf32(w.z); bp[3] = to_tf32(w.w);
        }

        // ---- gather / copy A slice [128][DIN] ----
#pragma unroll
        for (int it = 0; it < NIT; it++) {
            int nl = it * NPI + nl0;
            int node = nbase + nl;
            bool valid = node < N;
            float* ar = sA + nl * S2 + g * 4;
            float4 o;
            if (seg < NSEG) {
                int beg = 0, end = 0;
                if (valid) { beg = rps[seg][node]; end = rps[seg][node + 1]; }
                float4 acc4 = make_float4(0.f, 0.f, 0.f, 0.f);
                const float* sp = ss[seg] + g * 4;
                const int* ci = cis[seg];
                int e = beg;
                for (; e + 2 <= end; e += 2) {
                    int i0 = ci[e], i1 = ci[e + 1];
                    float4 v0 = *reinterpret_cast<const float4*>(sp + (size_t)i0 * DIN);
                    float4 v1 = *reinterpret_cast<const float4*>(sp + (size_t)i1 * DIN);
                    acc4.x += v0.x + v1.x; acc4.y += v0.y + v1.y;
                    acc4.z += v0.z + v1.z; acc4.w += v0.w + v1.w;
                }
                if (e < end) {
                    int i0 = ci[e];
                    float4 v0 = *reinterpret_cast<const float4*>(sp + (size_t)i0 * DIN);
                    acc4.x += v0.x; acc4.y += v0.y; acc4.z += v0.z; acc4.w += v0.w;
                }
                float inv = (end > beg) ? 1.0f / (float)(end - beg) : 0.0f;
                o.x = to_tf32(acc4.x * inv); o.y = to_tf32(acc4.y * inv);
                o.z = to_tf32(acc4.z * inv); o.w = to_tf32(acc4.w * inv);
            } else {
                float4 xs = make_float4(0.f, 0.f, 0.f, 0.f);
                if (valid) xs = *reinterpret_cast<const float4*>(xself + (size_t)node * DIN + g * 4);
                o.x = to_tf32(xs.x); o.y = to_tf32(xs.y); o.z = to_tf32(xs.z); o.w = to_tf32(xs.w);
            }
            ar[0] = o.x; ar[1] = o.y; ar[2] = o.z; ar[3] = o.w;
        }
        __syncthreads();

        // ---- mma over this K-chunk ----
#pragma unroll
        for (int k0 = 0; k0 < DIN; k0 += 8) {
            uint32_t bf[2][2];
#pragma unroll
            for (int ni = 0; ni < 2; ni++) {
                const float* pb = sB + (wn * 16 + ni * 8 + r) * S2 + k0 + c;
                bf[ni][0] = __float_as_uint(pb[0]);
                bf[ni][1] = __float_as_uint(pb[4]);
            }
#pragma unroll
            for (int mi = 0; mi < 2; mi++) {
                const float* pav = sA + (wm * 32 + mi * 16 + r) * S2 + k0 + c;
                uint32_t a0 = __float_as_uint(pav[0]);
                uint32_t a1 = __float_as_uint(pav[8 * S2]);
                uint32_t a2 = __float_as_uint(pav[4]);
                uint32_t a3 = __float_as_uint(pav[8 * S2 + 4]);
#pragma unroll
                for (int ni = 0; ni < 2; ni++)
                    mma_tf32(acc[mi][ni][0], acc[mi][ni][1], acc[mi][ni][2], acc[mi][ni][3],
                             a0, a1, a2, a3, bf[ni][0], bf[ni][1]);
            }
        }
        __syncthreads();
    }

    // ---- epilogue ----
    if (mode == 0) {
#pragma unroll
        for (int mi = 0; mi < 2; mi++) {
            int m0 = nbase + wm * 32 + mi * 16 + r;
#pragma unroll
            for (int ni = 0; ni < 2; ni++) {
                int col = wn * 16 + ni * 8 + 2 * c;
                if (m0 < N) {
                    float2 v = make_float2(fmaxf(acc[mi][ni][0], 0.f), fmaxf(acc[mi][ni][1], 0.f));
                    *reinterpret_cast<float2*>(out + (size_t)m0 * 64 + col) = v;
                }
                if (m0 + 8 < N) {
                    float2 v = make_float2(fmaxf(acc[mi][ni][2], 0.f), fmaxf(acc[mi][ni][3], 0.f));
                    *reinterpret_cast<float2*>(out + (size_t)(m0 + 8) * 64 + col) = v;
                }
            }
        }
    } else {
        float lb = linb[0];
        float ap = pa[0];
        float pl[2] = {0.f, 0.f}, ph[2] = {0.f, 0.f};
#pragma unroll
        for (int mi = 0; mi < 2; mi++) {
#pragma unroll
            for (int ni = 0; ni < 2; ni++) {
                int col = wn * 16 + ni * 8 + 2 * c;
                float w0 = linW[col], w1 = linW[col + 1];
                pl[mi] += fmaxf(acc[mi][ni][0], 0.f) * w0 + fmaxf(acc[mi][ni][1], 0.f) * w1;
                ph[mi] += fmaxf(acc[mi][ni][2], 0.f) * w0 + fmaxf(acc[mi][ni][3], 0.f) * w1;
            }
            pl[mi] += __shfl_xor_sync(0xffffffffu, pl[mi], 1);
            pl[mi] += __shfl_xor_sync(0xffffffffu, pl[mi], 2);
            ph[mi] += __shfl_xor_sync(0xffffffffu, ph[mi], 1);
            ph[mi] += __shfl_xor_sync(0xffffffffu, ph[mi], 2);
        }
        if (c == 0) {
#pragma unroll
            for (int mi = 0; mi < 2; mi++) {
                sred[wn * 128 + wm * 32 + mi * 16 + r] = pl[mi];
                sred[wn * 128 + wm * 32 + mi * 16 + r + 8] = ph[mi];
            }
        }
        __syncthreads();
        if (tid < 128) {
            float v = sred[tid] + sred[128 + tid] + sred[256 + tid] + sred[384 + tid] + lb;
            int n = nbase + tid;
            if (n < N) out[n] = (v >= 0.f) ? v : ap * v;
        }
    }
}

// ---------------- launch ----------------
extern "C" void kernel_launch(void* const* d_in, const int* in_sizes, int n_in,
                              void* d_out, int out_size) {
    const float* x_pf = (const float*)d_in[0];
    const float* x_gw = (const float*)d_in[1];
    const float* x_sw = (const float*)d_in[2];
    const float* W1l  = (const float*)d_in[3];
    const float* b1l  = (const float*)d_in[4];
    const float* W1r  = (const float*)d_in[5];
    const float* W2l  = (const float*)d_in[6];
    const float* b2l  = (const float*)d_in[7];
    const float* W2r  = (const float*)d_in[8];
    const float* linW = (const float*)d_in[9];
    const float* linb = (const float*)d_in[10];
    const float* pa   = (const float*)d_in[11];
    const int* eis[7] = {
        (const int*)d_in[12],  // pf_gw
        (const int*)d_in[16],  // sw_gw
        (const int*)d_in[18],  // gw_gw
        (const int*)d_in[13],  // gw_pf
        (const int*)d_in[15],  // sw_pf
        (const int*)d_in[14],  // pf_sw
        (const int*)d_in[17],  // gw_sw
    };
    float* out = (float*)d_out;
    int E = in_sizes[12] / 2;

    float* scr;
    cudaGetSymbolAddress((void**)&scr, g_scratch);

    float* h1_pf = scr + OFF_H1;
    float* h1_gw = h1_pf + (size_t)NPF * 64;
    float* h1_sw = h1_gw + (size_t)NGW * 64;

    int* cnt_base    = (int*)(scr + OFF_CNT);
    int* fill_base   = (int*)(scr + OFF_FILL);
    int* incl        = (int*)(scr + OFF_INCL);
    int* bsums       = (int*)(scr + OFF_BSUMS);
    int* rowptr_base = (int*)(scr + OFF_ROWPTR);
    int* colidx_base = (int*)(scr + OFF_COLIDX);

    const int ns[7] = {NGW, NGW, NGW, NPF, NPF, NSW, NSW};
    ScanCfg sc;
    int cnt_pad_total = 0;
    {
        int po = 0, ro = 0;
        for (int t = 0; t < 7; t++) {
            sc.ps[t] = po;
            sc.n[t] = ns[t];
            sc.nblk[t] = (ns[t] + 1023) / 1024;
            sc.rpo[t] = ro;
            po += sc.nblk[t] * 1024;
            ro += ns[t] + 1;
        }
        cnt_pad_total = po;
    }

    Ptrs7i pei, prp;
    Ptrs7o pcnt, pfill, pcol;
    int* rps[7]; int* cols[7];
    for (int t = 0; t < 7; t++) {
        pei.p[t]  = eis[t];
        pcnt.p[t] = cnt_base + sc.ps[t];
        pfill.p[t] = fill_base + sc.ps[t];
        rps[t] = rowptr_base + sc.rpo[t];
        prp.p[t] = rps[t];
        cols[t] = colidx_base + (size_t)t * EMAX;
        pcol.p[t] = cols[t];
    }

    float* wbase  = scr + OFF_WCAT;
    float* wL1_gw = wbase;
    float* wL1_pf = wL1_gw + 8192;
    float* wL1_sw = wL1_pf + 6144;
    float* wL2_gw = wL1_sw + 6144;
    float* wL2_pf = wL2_gw + 16384;
    float* wL2_sw = wL2_pf + 12288;
    float* bL1_gw = wL2_sw + 12288;
    float* bL1_pf = bL1_gw + 64;
    float* bL1_sw = bL1_pf + 64;
    float* bL2_gw = bL1_sw + 64;
    float* bL2_pf = bL2_gw + 64;
    float* bL2_sw = bL2_pf + 64;

    // ---- CSR build ----
    cudaMemsetAsync(cnt_base, 0, (size_t)cnt_pad_total * sizeof(int), 0);
    cudaMemsetAsync(fill_base, 0, (size_t)cnt_pad_total * sizeof(int), 0);
    {
        dim3 g((E + 255) / 256, 7);
        count_all<<<g, 256>>>(pei, pcnt, E);
    }
    {
        dim3 g(300, 7);
        scan_partial<<<g, 1024>>>(cnt_base, incl, bsums, sc);
        dim3 g2(1, 7);
        scan_bsums<<<g2, 512>>>(bsums, sc);
        dim3 g3((NGW + 255) / 256, 7);
        scan_final<<<g3, 256>>>(incl, bsums, rowptr_base, sc);
    }
    {
        dim3 g((E + 255) / 256, 7);
        scatter_all<<<g, 256>>>(pei, prp, pfill, pcol, E);
    }

    // ---- weights ----
    {
        WAll wa;
        wa.c[0] = {W1l, W1r, b1l, wL1_gw, bL1_gw, 32, 3, 7, 0, 4, 6};
        wa.c[1] = {W1l, W1r, b1l, wL1_pf, bL1_pf, 32, 2, 9, 1, 3, -1};
        wa.c[2] = {W1l, W1r, b1l, wL1_sw, bL1_sw, 32, 2, 8, 2, 5, -1};
        wa.c[3] = {W2l, W2r, b2l, wL2_gw, bL2_gw, 64, 3, 7, 0, 4, 6};
        wa.c[4] = {W2l, W2r, b2l, wL2_pf, bL2_pf, 64, 2, 9, 1, 3, -1};
        wa.c[5] = {W2l, W2r, b2l, wL2_sw, bL2_sw, 64, 2, 8, 2, 5, -1};
        dim3 g(64, 6);
        build_wcat_all<<<g, 256>>>(wa);
    }

    // ---- layer 1: fused gather+GEMM (Din=32) ----
    fused_layer<32, 3><<<(NGW + 127) / 128, 512>>>(
        rps[0], cols[0], x_pf, rps[1], cols[1], x_sw, rps[2], cols[2], x_gw,
        x_gw, NGW, wL1_gw, bL1_gw, 0, h1_gw, nullptr, nullptr, nullptr);
    fused_layer<32, 2><<<(NPF + 127) / 128, 512>>>(
        rps[3], cols[3], x_gw, rps[4], cols[4], x_sw, nullptr, nullptr, nullptr,
        x_pf, NPF, wL1_pf, bL1_pf, 0, h1_pf, nullptr, nullptr, nullptr);
    fused_layer<32, 2><<<(NSW + 127) / 128, 512>>>(
        rps[5], cols[5], x_pf, rps[6], cols[6], x_gw, nullptr, nullptr, nullptr,
        x_sw, NSW, wL1_sw, bL1_sw, 0, h1_sw, nullptr, nullptr, nullptr);

    // ---- layer 2: fused gather+GEMM (Din=64) ----
    // out layout: out_gw [NGW], out_sw [NSW], h_pf [NPF*64]
    fused_layer<64, 3><<<(NGW + 127) / 128, 512>>>(
        rps[0], cols[0], h1_pf, rps[1], cols[1], h1_sw, rps[2], cols[2], h1_gw,
        h1_gw, NGW, wL2_gw, bL2_gw, 1, out, linW, linb, pa);
    fused_layer<64, 2><<<(NSW + 127) / 128, 512>>>(
        rps[5], cols[5], h1_pf, rps[6], cols[6], h1_gw, nullptr, nullptr, nullptr,
        h1_sw, NSW, wL2_sw, bL2_sw, 1, out + NGW, linW, linb, pa);
    fused_layer<64, 2><<<(NPF + 127) / 128, 512>>>(
        rps[3], cols[3], h1_gw, rps[4], cols[4], h1_sw, nullptr, nullptr, nullptr,
        h1_pf, NPF, wL2_pf, bL2_pf, 0, out + NGW + NSW, nullptr, nullptr, nullptr);
}

// round 9
// speedup vs baseline: 1.5783x; 1.0232x over previous
#include <cuda_runtime.h>
#include <cstddef>
#include <cstdint>

#define NPF 60000
#define NGW 300000
#define NSW 60000
#define EMAX 1000000

// ---------------- scratch layout (4-byte units, ALL multiples of 4) ----------------
static const size_t OFF_H1     = 0;           // 26,880,000 floats
static const size_t OFF_CNT    = 26880000;    // padded per-type regions (1,163,264)
static const size_t OFF_FILL   = 28043264;
static const size_t OFF_INCL   = 29206528;
static const size_t OFF_BSUMS  = 30369792;    // 7*512
static const size_t OFF_ROWPTR = 30373376;    // 1,140,007 used, padded to 1,140,008
static const size_t OFF_COLIDX = 31513384;    // 7,000,000
static const size_t OFF_WCAT   = 38513384;    // ~62,000 (16B aligned)

__device__ float g_scratch[38600000];   // ~155 MB

// types: 0 pf_gw, 1 sw_gw, 2 gw_gw, 3 gw_pf, 4 sw_pf, 5 pf_sw, 6 gw_sw
struct ScanCfg { int ps[7]; int nblk[7]; int n[7]; int rpo[7]; };
struct Ptrs7i { const int* p[7]; };
struct Ptrs7o { int* p[7]; };

// ---------------- CSR build (batched) ----------------
__global__ void count_all(Ptrs7i ei, Ptrs7o cnt, int E) {
    int t = blockIdx.y;
    int i = blockIdx.x * blockDim.x + threadIdx.x;
    if (i < E) atomicAdd(&cnt.p[t][ei.p[t][E + i]], 1);
}

__global__ void scan_partial(const int* __restrict__ cnt, int* __restrict__ incl,
                             int* __restrict__ bsums, ScanCfg sc) {
    int t = blockIdx.y;
    if ((int)blockIdx.x >= sc.nblk[t]) return;
    __shared__ int s[1024];
    int tid = threadIdx.x;
    int base = sc.ps[t] + blockIdx.x * 1024;
    int v = cnt[base + tid];
    s[tid] = v; __syncthreads();
#pragma unroll
    for (int off = 1; off < 1024; off <<= 1) {
        int t2 = (tid >= off) ? s[tid - off] : 0;
        __syncthreads();
        s[tid] += t2;
        __syncthreads();
    }
    incl[base + tid] = s[tid];
    if (tid == 1023) bsums[t * 512 + blockIdx.x] = s[1023];
}

__global__ void scan_bsums(int* __restrict__ bs, ScanCfg sc) {
    int t = blockIdx.y;
    int nb = sc.nblk[t];
    __shared__ int s[512];
    int tid = threadIdx.x;
    int v = (tid < nb) ? bs[t * 512 + tid] : 0;
    s[tid] = v; __syncthreads();
#pragma unroll
    for (int off = 1; off < 512; off <<= 1) {
        int t2 = (tid >= off) ? s[tid - off] : 0;
        __syncthreads();
        s[tid] += t2;
        __syncthreads();
    }
    if (tid < nb) bs[t * 512 + tid] = s[tid] - v;   // exclusive
}

__global__ void scan_final(const int* __restrict__ incl, const int* __restrict__ bs,
                           int* __restrict__ rowptr, ScanCfg sc) {
    int t = blockIdx.y;
    int i = blockIdx.x * blockDim.x + threadIdx.x;
    int n = sc.n[t];
    if (i < n) rowptr[sc.rpo[t] + i + 1] = incl[sc.ps[t] + i] + bs[t * 512 + (i >> 10)];
    if (i == 0) rowptr[sc.rpo[t]] = 0;
}

__global__ void scatter_all(Ptrs7i ei, Ptrs7i rp, Ptrs7o fill, Ptrs7o col, int E) {
    int t = blockIdx.y;
    int i = blockIdx.x * blockDim.x + threadIdx.x;
    if (i < E) {
        int s = ei.p[t][i];
        int d = ei.p[t][E + i];
        int pos = rp.p[t][d] + atomicAdd(&fill.p[t][d], 1);
        col.p[t][pos] = s;
    }
}

// ---------------- combined weights (batched) ----------------
struct WCfg {
    const float* Wl; const float* Wr; const float* b;
    float* w; float* bc;
    int Din, nm, selfid, m0, m1, m2;
};
struct WAll { WCfg c[6]; };

__global__ void build_wcat_all(WAll wa) {
    WCfg cf = wa.c[blockIdx.y];
    int K = (cf.nm + 1) * cf.Din;
    int idx = blockIdx.x * blockDim.x + threadIdx.x;
    if (idx >= 64 * K) return;
    int d = idx / K, c = idx % K;
    int seg = c / cf.Din, k = c % cf.Din;
    int ms[3] = {cf.m0, cf.m1, cf.m2};
    int stride = 64 * cf.Din;
    float v;
    if (seg < cf.nm) {
        v = cf.Wl[ms[seg] * stride + d * cf.Din + k];
    } else {
        v = cf.Wl[cf.selfid * stride + d * cf.Din + k] + cf.Wr[cf.selfid * stride + d * cf.Din + k];
        for (int i = 0; i < cf.nm; i++) v += cf.Wr[ms[i] * stride + d * cf.Din + k];
    }
    cf.w[d * K + c] = v;
    if (c == 0) {
        float bb = cf.b[cf.selfid * 64 + d];
        for (int i = 0; i < cf.nm; i++) bb += cf.b[ms[i] * 64 + d];
        cf.bc[d] = bb;
    }
}

// ---------------- fused gather + tf32 GEMM (segment-streamed, multi-type) -------------
__device__ __forceinline__ float to_tf32(float x) {
    float r;
    asm("cvt.rna.tf32.f32 %0, %1;" : "=f"(r) : "f"(x));
    return r;
}

__device__ __forceinline__ void mma_tf32(float& d0, float& d1, float& d2, float& d3,
                                         uint32_t a0, uint32_t a1, uint32_t a2, uint32_t a3,
                                         uint32_t b0, uint32_t b1) {
    asm volatile("mma.sync.aligned.m16n8k8.row.col.f32.tf32.tf32.f32 "
                 "{%0,%1,%2,%3}, {%4,%5,%6,%7}, {%8,%9}, {%0,%1,%2,%3};"
                 : "+f"(d0), "+f"(d1), "+f"(d2), "+f"(d3)
                 : "r"(a0), "r"(a1), "r"(a2), "r"(a3), "r"(b0), "r"(b1));
}

struct TypeParams {
    const int* rp[3];
    const int* ci[3];
    const float* src[3];
    const float* xself;
    const float* wcat;
    const float* bcat;
    float* out;
    int N;
    int nseg;     // edge-type segments (2 or 3)
    int K;        // (nseg+1)*DIN
    int mode;     // 0: write [N,64]; 1: prelu(dot(relu(h),linW)+linb)
    int blk0;     // first blockIdx.x for this type
};
struct LayerParams {
    TypeParams t[3];
    const float* linW; const float* linb; const float* pa;
};

// Per block: 128 dst nodes of one type. Segment-streamed K.
template <int DIN>
__global__ void __launch_bounds__(512, 2) fused_multi(LayerParams lp) {
    constexpr int S2 = DIN + 4;
    constexpr int G = DIN / 4;
    constexpr int NPI = 512 / G;
    constexpr int NIT = 128 / NPI;
    constexpr int C4 = DIN / 4;
    constexpr int BL = (64 * C4) / 512;   // 1 (DIN=32) or 2 (DIN=64)

    __shared__ float sA[128 * S2];
    __shared__ float sB[64 * S2];
    __shared__ float sred[512];

    int bx = blockIdx.x;
    int ty = (bx >= lp.t[2].blk0) ? 2 : (bx >= lp.t[1].blk0) ? 1 : 0;
    const TypeParams& tp = lp.t[ty];
    int nbase = (bx - tp.blk0) * 128;
    int N = tp.N;
    int nseg = tp.nseg;
    int K = tp.K;

    int tid = threadIdx.x;
    int warp = tid >> 5, lane = tid & 31;
    int wm = warp >> 2, wn = warp & 3;
    int r = lane >> 2, c = lane & 3;

    float acc[2][2][4];
#pragma unroll
    for (int mi = 0; mi < 2; mi++)
#pragma unroll
        for (int ni = 0; ni < 2; ni++) {
            int col = wn * 16 + ni * 8 + 2 * c;
            acc[mi][ni][0] = acc[mi][ni][2] = tp.bcat[col];
            acc[mi][ni][1] = acc[mi][ni][3] = tp.bcat[col + 1];
        }

    int g = tid & (G - 1);
    int nl0 = tid / G;

    for (int seg = 0; seg <= nseg; seg++) {
        bool isself = (seg == nseg);
        const int* rp = tp.rp[isself ? 0 : seg];
        const int* ci = tp.ci[isself ? 0 : seg];
        const float* src = tp.src[isself ? 0 : seg];

        // ---- stage weight slice [64][DIN] ----
#pragma unroll
        for (int j = 0; j < BL; j++) {
            int idx = j * 512 + tid;
            int row = idx / C4, cc = idx % C4;
            float4 w = *reinterpret_cast<const float4*>(tp.wcat + (size_t)row * K + seg * DIN + cc * 4);
            float* bp = sB + row * S2 + cc * 4;
            bp[0] = to_tf32(w.x); bp[1] = to_tf32(w.y); bp[2] = to_tf32(w.z); bp[3] = to_tf32(w.w);
        }

        // ---- gather / copy A slice [128][DIN] ----
#pragma unroll
        for (int it = 0; it < NIT; it++) {
            int nl = it * NPI + nl0;
            int node = nbase + nl;
            bool valid = node < N;
            float* ar = sA + nl * S2 + g * 4;
            float4 o;
            if (!isself) {
                int beg = 0, end = 0;
                if (valid) { beg = rp[node]; end = rp[node + 1]; }
                float4 a4 = make_float4(0.f, 0.f, 0.f, 0.f);
                const float* sp = src + g * 4;
                int e = beg;
                for (; e + 4 <= end; e += 4) {
                    int i0 = ci[e], i1 = ci[e + 1], i2 = ci[e + 2], i3 = ci[e + 3];
                    float4 v0 = *reinterpret_cast<const float4*>(sp + (size_t)i0 * DIN);
                    float4 v1 = *reinterpret_cast<const float4*>(sp + (size_t)i1 * DIN);
                    float4 v2 = *reinterpret_cast<const float4*>(sp + (size_t)i2 * DIN);
                    float4 v3 = *reinterpret_cast<const float4*>(sp + (size_t)i3 * DIN);
                    a4.x += (v0.x + v1.x) + (v2.x + v3.x);
                    a4.y += (v0.y + v1.y) + (v2.y + v3.y);
                    a4.z += (v0.z + v1.z) + (v2.z + v3.z);
                    a4.w += (v0.w + v1.w) + (v2.w + v3.w);
                }
                for (; e < end; e++) {
                    int i0 = ci[e];
                    float4 v0 = *reinterpret_cast<const float4*>(sp + (size_t)i0 * DIN);
                    a4.x += v0.x; a4.y += v0.y; a4.z += v0.z; a4.w += v0.w;
                }
                float inv = (end > beg) ? 1.0f / (float)(end - beg) : 0.0f;
                o.x = to_tf32(a4.x * inv); o.y = to_tf32(a4.y * inv);
                o.z = to_tf32(a4.z * inv); o.w = to_tf32(a4.w * inv);
            } else {
                float4 xs = make_float4(0.f, 0.f, 0.f, 0.f);
                if (valid) xs = *reinterpret_cast<const float4*>(tp.xself + (size_t)node * DIN + g * 4);
                o.x = to_tf32(xs.x); o.y = to_tf32(xs.y); o.z = to_tf32(xs.z); o.w = to_tf32(xs.w);
            }
            ar[0] = o.x; ar[1] = o.y; ar[2] = o.z; ar[3] = o.w;
        }
        __syncthreads();

        // ---- mma over this K-chunk ----
#pragma unroll
        for (int k0 = 0; k0 < DIN; k0 += 8) {
            uint32_t bf[2][2];
#pragma unroll
            for (int ni = 0; ni < 2; ni++) {
                const float* pb = sB + (wn * 16 + ni * 8 + r) * S2 + k0 + c;
                bf[ni][0] = __float_as_uint(pb[0]);
                bf[ni][1] = __float_as_uint(pb[4]);
            }
#pragma unroll
            for (int mi = 0; mi < 2; mi++) {
                const float* pav = sA + (wm * 32 + mi * 16 + r) * S2 + k0 + c;
                uint32_t a0 = __float_as_uint(pav[0]);
                uint32_t a1 = __float_as_uint(pav[8 * S2]);
                uint32_t a2 = __float_as_uint(pav[4]);
                uint32_t a3 = __float_as_uint(pav[8 * S2 + 4]);
#pragma unroll
                for (int ni = 0; ni < 2; ni++)
                    mma_tf32(acc[mi][ni][0], acc[mi][ni][1], acc[mi][ni][2], acc[mi][ni][3],
                             a0, a1, a2, a3, bf[ni][0], bf[ni][1]);
            }
        }
        __syncthreads();
    }

    // ---- epilogue ----
    float* out = tp.out;
    if (tp.mode == 0) {
#pragma unroll
        for (int mi = 0; mi < 2; mi++) {
            int m0 = nbase + wm * 32 + mi * 16 + r;
#pragma unroll
            for (int ni = 0; ni < 2; ni++) {
                int col = wn * 16 + ni * 8 + 2 * c;
                if (m0 < N) {
                    float2 v = make_float2(fmaxf(acc[mi][ni][0], 0.f), fmaxf(acc[mi][ni][1], 0.f));
                    *reinterpret_cast<float2*>(out + (size_t)m0 * 64 + col) = v;
                }
                if (m0 + 8 < N) {
                    float2 v = make_float2(fmaxf(acc[mi][ni][2], 0.f), fmaxf(acc[mi][ni][3], 0.f));
                    *reinterpret_cast<float2*>(out + (size_t)(m0 + 8) * 64 + col) = v;
                }
            }
        }
    } else {
        float lb = lp.linb[0];
        float ap = lp.pa[0];
        float pl[2] = {0.f, 0.f}, ph[2] = {0.f, 0.f};
#pragma unroll
        for (int mi = 0; mi < 2; mi++) {
#pragma unroll
            for (int ni = 0; ni < 2; ni++) {
                int col = wn * 16 + ni * 8 + 2 * c;
                float w0 = lp.linW[col], w1 = lp.linW[col + 1];
                pl[mi] += fmaxf(acc[mi][ni][0], 0.f) * w0 + fmaxf(acc[mi][ni][1], 0.f) * w1;
                ph[mi] += fmaxf(acc[mi][ni][2], 0.f) * w0 + fmaxf(acc[mi][ni][3], 0.f) * w1;
            }
            pl[mi] += __shfl_xor_sync(0xffffffffu, pl[mi], 1);
            pl[mi] += __shfl_xor_sync(0xffffffffu, pl[mi], 2);
            ph[mi] += __shfl_xor_sync(0xffffffffu, ph[mi], 1);
            ph[mi] += __shfl_xor_sync(0xffffffffu, ph[mi], 2);
        }
        if (c == 0) {
#pragma unroll
            for (int mi = 0; mi < 2; mi++) {
                sred[wn * 128 + wm * 32 + mi * 16 + r] = pl[mi];
                sred[wn * 128 + wm * 32 + mi * 16 + r + 8] = ph[mi];
            }
        }
        __syncthreads();
        if (tid < 128) {
            float v = sred[tid] + sred[128 + tid] + sred[256 + tid] + sred[384 + tid] + lb;
            int n = nbase + tid;
            if (n < N) out[n] = (v >= 0.f) ? v : ap * v;
        }
    }
}

// ---------------- launch ----------------
extern "C" void kernel_launch(void* const* d_in, const int* in_sizes, int n_in,
                              void* d_out, int out_size) {
    const float* x_pf = (const float*)d_in[0];
    const float* x_gw = (const float*)d_in[1];
    const float* x_sw = (const float*)d_in[2];
    const float* W1l  = (const float*)d_in[3];
    const float* b1l  = (const float*)d_in[4];
    const float* W1r  = (const float*)d_in[5];
    const float* W2l  = (const float*)d_in[6];
    const float* b2l  = (const float*)d_in[7];
    const float* W2r  = (const float*)d_in[8];
    const float* linW = (const float*)d_in[9];
    const float* linb = (const float*)d_in[10];
    const float* pa   = (const float*)d_in[11];
    const int* eis[7] = {
        (const int*)d_in[12],  // pf_gw
        (const int*)d_in[16],  // sw_gw
        (const int*)d_in[18],  // gw_gw
        (const int*)d_in[13],  // gw_pf
        (const int*)d_in[15],  // sw_pf
        (const int*)d_in[14],  // pf_sw
        (const int*)d_in[17],  // gw_sw
    };
    float* out = (float*)d_out;
    int E = in_sizes[12] / 2;

    float* scr;
    cudaGetSymbolAddress((void**)&scr, g_scratch);

    float* h1_pf = scr + OFF_H1;
    float* h1_gw = h1_pf + (size_t)NPF * 64;
    float* h1_sw = h1_gw + (size_t)NGW * 64;

    int* cnt_base    = (int*)(scr + OFF_CNT);
    int* fill_base   = (int*)(scr + OFF_FILL);
    int* incl        = (int*)(scr + OFF_INCL);
    int* bsums       = (int*)(scr + OFF_BSUMS);
    int* rowptr_base = (int*)(scr + OFF_ROWPTR);
    int* colidx_base = (int*)(scr + OFF_COLIDX);

    const int ns[7] = {NGW, NGW, NGW, NPF, NPF, NSW, NSW};
    ScanCfg sc;
    int cnt_pad_total = 0;
    {
        int po = 0, ro = 0;
        for (int t = 0; t < 7; t++) {
            sc.ps[t] = po;
            sc.n[t] = ns[t];
            sc.nblk[t] = (ns[t] + 1023) / 1024;
            sc.rpo[t] = ro;
            po += sc.nblk[t] * 1024;
            ro += ns[t] + 1;
        }
        cnt_pad_total = po;
    }

    Ptrs7i pei, prp;
    Ptrs7o pcnt, pfill, pcol;
    int* rps[7]; int* cols[7];
    for (int t = 0; t < 7; t++) {
        pei.p[t]  = eis[t];
        pcnt.p[t] = cnt_base + sc.ps[t];
        pfill.p[t] = fill_base + sc.ps[t];
        rps[t] = rowptr_base + sc.rpo[t];
        prp.p[t] = rps[t];
        cols[t] = colidx_base + (size_t)t * EMAX;
        pcol.p[t] = cols[t];
    }

    float* wbase  = scr + OFF_WCAT;
    float* wL1_gw = wbase;
    float* wL1_pf = wL1_gw + 8192;
    float* wL1_sw = wL1_pf + 6144;
    float* wL2_gw = wL1_sw + 6144;
    float* wL2_pf = wL2_gw + 16384;
    float* wL2_sw = wL2_pf + 12288;
    float* bL1_gw = wL2_sw + 12288;
    float* bL1_pf = bL1_gw + 64;
    float* bL1_sw = bL1_pf + 64;
    float* bL2_gw = bL1_sw + 64;
    float* bL2_pf = bL2_gw + 64;
    float* bL2_sw = bL2_pf + 64;

    // ---- CSR build ----
    cudaMemsetAsync(cnt_base, 0, (size_t)cnt_pad_total * sizeof(int), 0);
    cudaMemsetAsync(fill_base, 0, (size_t)cnt_pad_total * sizeof(int), 0);
    {
        dim3 g((E + 255) / 256, 7);
        count_all<<<g, 256>>>(pei, pcnt, E);
    }
    {
        dim3 g(300, 7);
        scan_partial<<<g, 1024>>>(cnt_base, incl, bsums, sc);
        dim3 g2(1, 7);
        scan_bsums<<<g2, 512>>>(bsums, sc);
        dim3 g3((NGW + 255) / 256, 7);
        scan_final<<<g3, 256>>>(incl, bsums, rowptr_base, sc);
    }
    {
        dim3 g((E + 255) / 256, 7);
        scatter_all<<<g, 256>>>(pei, prp, pfill, pcol, E);
    }

    // ---- weights ----
    {
        WAll wa;
        wa.c[0] = {W1l, W1r, b1l, wL1_gw, bL1_gw, 32, 3, 7, 0, 4, 6};
        wa.c[1] = {W1l, W1r, b1l, wL1_pf, bL1_pf, 32, 2, 9, 1, 3, -1};
        wa.c[2] = {W1l, W1r, b1l, wL1_sw, bL1_sw, 32, 2, 8, 2, 5, -1};
        wa.c[3] = {W2l, W2r, b2l, wL2_gw, bL2_gw, 64, 3, 7, 0, 4, 6};
        wa.c[4] = {W2l, W2r, b2l, wL2_pf, bL2_pf, 64, 2, 9, 1, 3, -1};
        wa.c[5] = {W2l, W2r, b2l, wL2_sw, bL2_sw, 64, 2, 8, 2, 5, -1};
        dim3 g(64, 6);
        build_wcat_all<<<g, 256>>>(wa);
    }

    const int BGW = (NGW + 127) / 128;   // 2344
    const int BPF = (NPF + 127) / 128;   // 469
    const int BSW = (NSW + 127) / 128;   // 469
    const int BTOT = BGW + BPF + BSW;    // 3282

    // ---- layer 1 (Din=32): one launch, 3 types ----
    {
        LayerParams lp;
        lp.linW = linW; lp.linb = linb; lp.pa = pa;
        // gw: segs pf_gw(0), sw_gw(1), gw_gw(2); self x_gw
        lp.t[0] = {{rps[0], rps[1], rps[2]}, {cols[0], cols[1], cols[2]},
                   {x_pf, x_sw, x_gw}, x_gw, wL1_gw, bL1_gw, h1_gw,
                   NGW, 3, 128, 0, 0};
        // pf: segs gw_pf(3), sw_pf(4); self x_pf
        lp.t[1] = {{rps[3], rps[4], rps[4]}, {cols[3], cols[4], cols[4]},
                   {x_gw, x_sw, x_sw}, x_pf, wL1_pf, bL1_pf, h1_pf,
                   NPF, 2, 96, 0, BGW};
        // sw: segs pf_sw(5), gw_sw(6); self x_sw
        lp.t[2] = {{rps[5], rps[6], rps[6]}, {cols[5], cols[6], cols[6]},
                   {x_pf, x_gw, x_gw}, x_sw, wL1_sw, bL1_sw, h1_sw,
                   NSW, 2, 96, 0, BGW + BPF};
        fused_multi<32><<<BTOT, 512>>>(lp);
    }

    // ---- layer 2 (Din=64): one launch, 3 types ----
    // out layout: out_gw [NGW], out_sw [NSW], h_pf [NPF*64]
    {
        LayerParams lp;
        lp.linW = linW; lp.linb = linb; lp.pa = pa;
        lp.t[0] = {{rps[0], rps[1], rps[2]}, {cols[0], cols[1], cols[2]},
                   {h1_pf, h1_sw, h1_gw}, h1_gw, wL2_gw, bL2_gw, out,
                   NGW, 3, 256, 1, 0};
        lp.t[1] = {{rps[3], rps[4], rps[4]}, {cols[3], cols[4], cols[4]},
                   {h1_gw, h1_sw, h1_sw}, h1_pf, wL2_pf, bL2_pf, out + NGW + NSW,
                   NPF, 2, 192, 0, BGW};
        lp.t[2] = {{rps[5], rps[6], rps[6]}, {cols[5], cols[6], cols[6]},
                   {h1_pf, h1_gw, h1_gw}, h1_sw, wL2_sw, bL2_sw, out + NGW,
                   NSW, 2, 192, 1, BGW + BPF};
        fused_multi<64><<<BTOT, 512>>>(lp);
    }
}

// round 10
// speedup vs baseline: 1.5871x; 1.0056x over previous
#include <cuda_runtime.h>
#include <cstddef>
#include <cstdint>

#define NPF 60000
#define NGW 300000
#define NSW 60000
#define EMAX 1000000

// ---------------- scratch layout (4-byte units, ALL multiples of 4) ----------------
static const size_t OFF_H1     = 0;           // 26,880,000 floats
static const size_t OFF_CNT    = 26880000;    // padded per-type regions (1,163,264)
static const size_t OFF_FILL   = 28043264;
static const size_t OFF_INCL   = 29206528;
static const size_t OFF_BSUMS  = 30369792;    // 7*512
static const size_t OFF_ROWPTR = 30373376;    // 1,140,007 used, padded to 1,140,008
static const size_t OFF_COLIDX = 31513384;    // 7,000,000
static const size_t OFF_WCAT   = 38513384;    // ~62,000 (16B aligned)

__device__ float g_scratch[38600000];   // ~155 MB

// types: 0 pf_gw, 1 sw_gw, 2 gw_gw, 3 gw_pf, 4 sw_pf, 5 pf_sw, 6 gw_sw
struct ScanCfg { int ps[7]; int nblk[7]; int n[7]; int rpo[7]; };
struct Ptrs7i { const int* p[7]; };
struct Ptrs7o { int* p[7]; };

// ---------------- CSR build (batched) ----------------
__global__ void count_all(Ptrs7i ei, Ptrs7o cnt, int E) {
    int t = blockIdx.y;
    int i = blockIdx.x * blockDim.x + threadIdx.x;
    if (i < E) atomicAdd(&cnt.p[t][ei.p[t][E + i]], 1);
}

__global__ void scan_partial(const int* __restrict__ cnt, int* __restrict__ incl,
                             int* __restrict__ bsums, ScanCfg sc) {
    int t = blockIdx.y;
    if ((int)blockIdx.x >= sc.nblk[t]) return;
    __shared__ int s[1024];
    int tid = threadIdx.x;
    int base = sc.ps[t] + blockIdx.x * 1024;
    int v = cnt[base + tid];
    s[tid] = v; __syncthreads();
#pragma unroll
    for (int off = 1; off < 1024; off <<= 1) {
        int t2 = (tid >= off) ? s[tid - off] : 0;
        __syncthreads();
        s[tid] += t2;
        __syncthreads();
    }
    incl[base + tid] = s[tid];
    if (tid == 1023) bsums[t * 512 + blockIdx.x] = s[1023];
}

__global__ void scan_bsums(int* __restrict__ bs, ScanCfg sc) {
    int t = blockIdx.y;
    int nb = sc.nblk[t];
    __shared__ int s[512];
    int tid = threadIdx.x;
    int v = (tid < nb) ? bs[t * 512 + tid] : 0;
    s[tid] = v; __syncthreads();
#pragma unroll
    for (int off = 1; off < 512; off <<= 1) {
        int t2 = (tid >= off) ? s[tid - off] : 0;
        __syncthreads();
        s[tid] += t2;
        __syncthreads();
    }
    if (tid < nb) bs[t * 512 + tid] = s[tid] - v;   // exclusive
}

__global__ void scan_final(const int* __restrict__ incl, const int* __restrict__ bs,
                           int* __restrict__ rowptr, ScanCfg sc) {
    int t = blockIdx.y;
    int i = blockIdx.x * blockDim.x + threadIdx.x;
    int n = sc.n[t];
    if (i < n) rowptr[sc.rpo[t] + i + 1] = incl[sc.ps[t] + i] + bs[t * 512 + (i >> 10)];
    if (i == 0) rowptr[sc.rpo[t]] = 0;
}

__global__ void scatter_all(Ptrs7i ei, Ptrs7i rp, Ptrs7o fill, Ptrs7o col, int E) {
    int t = blockIdx.y;
    int i = blockIdx.x * blockDim.x + threadIdx.x;
    if (i < E) {
        int s = ei.p[t][i];
        int d = ei.p[t][E + i];
        int pos = rp.p[t][d] + atomicAdd(&fill.p[t][d], 1);
        col.p[t][pos] = s;
    }
}

// ---------------- combined weights (batched) ----------------
struct WCfg {
    const float* Wl; const float* Wr; const float* b;
    float* w; float* bc;
    int Din, nm, selfid, m0, m1, m2;
};
struct WAll { WCfg c[6]; };

__global__ void build_wcat_all(WAll wa) {
    WCfg cf = wa.c[blockIdx.y];
    int K = (cf.nm + 1) * cf.Din;
    int idx = blockIdx.x * blockDim.x + threadIdx.x;
    if (idx >= 64 * K) return;
    int d = idx / K, c = idx % K;
    int seg = c / cf.Din, k = c % cf.Din;
    int ms[3] = {cf.m0, cf.m1, cf.m2};
    int stride = 64 * cf.Din;
    float v;
    if (seg < cf.nm) {
        v = cf.Wl[ms[seg] * stride + d * cf.Din + k];
    } else {
        v = cf.Wl[cf.selfid * stride + d * cf.Din + k] + cf.Wr[cf.selfid * stride + d * cf.Din + k];
        for (int i = 0; i < cf.nm; i++) v += cf.Wr[ms[i] * stride + d * cf.Din + k];
    }
    cf.w[d * K + c] = v;
    if (c == 0) {
        float bb = cf.b[cf.selfid * 64 + d];
        for (int i = 0; i < cf.nm; i++) bb += cf.b[ms[i] * 64 + d];
        cf.bc[d] = bb;
    }
}

// ---------------- fused gather + tf32 GEMM (segment-streamed, multi-type) -------------
__device__ __forceinline__ float to_tf32(float x) {
    float r;
    asm("cvt.rna.tf32.f32 %0, %1;" : "=f"(r) : "f"(x));
    return r;
}

__device__ __forceinline__ void mma_tf32(float& d0, float& d1, float& d2, float& d3,
                                         uint32_t a0, uint32_t a1, uint32_t a2, uint32_t a3,
                                         uint32_t b0, uint32_t b1) {
    asm volatile("mma.sync.aligned.m16n8k8.row.col.f32.tf32.tf32.f32 "
                 "{%0,%1,%2,%3}, {%4,%5,%6,%7}, {%8,%9}, {%0,%1,%2,%3};"
                 : "+f"(d0), "+f"(d1), "+f"(d2), "+f"(d3)
                 : "r"(a0), "r"(a1), "r"(a2), "r"(a3), "r"(b0), "r"(b1));
}

struct TypeParams {
    const int* rp[3];
    const int* ci[3];
    const float* src[3];
    const float* xself;
    const float* wcat;
    const float* bcat;
    float* out;
    int N;
    int nseg;     // edge-type segments (2 or 3)
    int K;        // (nseg+1)*DIN
    int mode;     // 0: write [N,64]; 1: prelu(dot(relu(h),linW)+linb)
    int blk0;     // first blockIdx.x for this type
};
struct LayerParams {
    TypeParams t[3];
    const float* linW; const float* linb; const float* pa;
};

// Per block: 128 dst nodes of one type. Segment-streamed K.
template <int DIN>
__global__ void __launch_bounds__(512, 3) fused_multi(LayerParams lp) {
    constexpr int S2 = DIN + 4;
    constexpr int G = DIN / 4;
    constexpr int NPI = 512 / G;
    constexpr int NIT = 128 / NPI;
    constexpr int C4 = DIN / 4;
    constexpr int BL = (64 * C4) / 512;   // 1 (DIN=32) or 2 (DIN=64)

    __shared__ float sA[128 * S2];
    __shared__ float sB[64 * S2];
    __shared__ float sred[512];

    int bx = blockIdx.x;
    int ty = (bx >= lp.t[2].blk0) ? 2 : (bx >= lp.t[1].blk0) ? 1 : 0;
    const TypeParams& tp = lp.t[ty];
    int nbase = (bx - tp.blk0) * 128;
    int N = tp.N;
    int nseg = tp.nseg;
    int K = tp.K;

    int tid = threadIdx.x;
    int warp = tid >> 5, lane = tid & 31;
    int wm = warp >> 2, wn = warp & 3;
    int r = lane >> 2, c = lane & 3;

    float acc[2][2][4];
#pragma unroll
    for (int mi = 0; mi < 2; mi++)
#pragma unroll
        for (int ni = 0; ni < 2; ni++) {
            int col = wn * 16 + ni * 8 + 2 * c;
            acc[mi][ni][0] = acc[mi][ni][2] = tp.bcat[col];
            acc[mi][ni][1] = acc[mi][ni][3] = tp.bcat[col + 1];
        }

    int g = tid & (G - 1);
    int nl0 = tid / G;

    for (int seg = 0; seg <= nseg; seg++) {
        bool isself = (seg == nseg);
        const int* rp = tp.rp[isself ? 0 : seg];
        const int* ci = tp.ci[isself ? 0 : seg];
        const float* src = tp.src[isself ? 0 : seg];

        // ---- stage weight slice [64][DIN] ----
#pragma unroll
        for (int j = 0; j < BL; j++) {
            int idx = j * 512 + tid;
            int row = idx / C4, cc = idx % C4;
            float4 w = *reinterpret_cast<const float4*>(tp.wcat + (size_t)row * K + seg * DIN + cc * 4);
            float* bp = sB + row * S2 + cc * 4;
            bp[0] = to_tf32(w.x); bp[1] = to_tf32(w.y); bp[2] = to_tf32(w.z); bp[3] = to_tf32(w.w);
        }

        // ---- gather / copy A slice [128][DIN] ----
#pragma unroll
        for (int it = 0; it < NIT; it++) {
            int nl = it * NPI + nl0;
            int node = nbase + nl;
            bool valid = node < N;
            float* ar = sA + nl * S2 + g * 4;
            float4 o;
            if (!isself) {
                int beg = 0, end = 0;
                if (valid) { beg = rp[node]; end = rp[node + 1]; }
                float4 a4 = make_float4(0.f, 0.f, 0.f, 0.f);
                const float* sp = src + g * 4;
                int e = beg;
                for (; e + 4 <= end; e += 4) {
                    int i0 = ci[e], i1 = ci[e + 1], i2 = ci[e + 2], i3 = ci[e + 3];
                    float4 v0 = *reinterpret_cast<const float4*>(sp + (size_t)i0 * DIN);
                    float4 v1 = *reinterpret_cast<const float4*>(sp + (size_t)i1 * DIN);
                    float4 v2 = *reinterpret_cast<const float4*>(sp + (size_t)i2 * DIN);
                    float4 v3 = *reinterpret_cast<const float4*>(sp + (size_t)i3 * DIN);
                    a4.x += (v0.x + v1.x) + (v2.x + v3.x);
                    a4.y += (v0.y + v1.y) + (v2.y + v3.y);
                    a4.z += (v0.z + v1.z) + (v2.z + v3.z);
                    a4.w += (v0.w + v1.w) + (v2.w + v3.w);
                }
                for (; e < end; e++) {
                    int i0 = ci[e];
                    float4 v0 = *reinterpret_cast<const float4*>(sp + (size_t)i0 * DIN);
                    a4.x += v0.x; a4.y += v0.y; a4.z += v0.z; a4.w += v0.w;
                }
                float inv = (end > beg) ? 1.0f / (float)(end - beg) : 0.0f;
                o.x = to_tf32(a4.x * inv); o.y = to_tf32(a4.y * inv);
                o.z = to_tf32(a4.z * inv); o.w = to_tf32(a4.w * inv);
            } else {
                float4 xs = make_float4(0.f, 0.f, 0.f, 0.f);
                if (valid) xs = *reinterpret_cast<const float4*>(tp.xself + (size_t)node * DIN + g * 4);
                o.x = to_tf32(xs.x); o.y = to_tf32(xs.y); o.z = to_tf32(xs.z); o.w = to_tf32(xs.w);
            }
            ar[0] = o.x; ar[1] = o.y; ar[2] = o.z; ar[3] = o.w;
        }
        __syncthreads();

        // ---- mma over this K-chunk ----
#pragma unroll
        for (int k0 = 0; k0 < DIN; k0 += 8) {
            uint32_t bf[2][2];
#pragma unroll
            for (int ni = 0; ni < 2; ni++) {
                const float* pb = sB + (wn * 16 + ni * 8 + r) * S2 + k0 + c;
                bf[ni][0] = __float_as_uint(pb[0]);
                bf[ni][1] = __float_as_uint(pb[4]);
            }
#pragma unroll
            for (int mi = 0; mi < 2; mi++) {
                const float* pav = sA + (wm * 32 + mi * 16 + r) * S2 + k0 + c;
                uint32_t a0 = __float_as_uint(pav[0]);
                uint32_t a1 = __float_as_uint(pav[8 * S2]);
                uint32_t a2 = __float_as_uint(pav[4]);
                uint32_t a3 = __float_as_uint(pav[8 * S2 + 4]);
#pragma unroll
                for (int ni = 0; ni < 2; ni++)
                    mma_tf32(acc[mi][ni][0], acc[mi][ni][1], acc[mi][ni][2], acc[mi][ni][3],
                             a0, a1, a2, a3, bf[ni][0], bf[ni][1]);
            }
        }
        __syncthreads();
    }

    // ---- epilogue ----
    float* out = tp.out;
    if (tp.mode == 0) {
#pragma unroll
        for (int mi = 0; mi < 2; mi++) {
            int m0 = nbase + wm * 32 + mi * 16 + r;
#pragma unroll
            for (int ni = 0; ni < 2; ni++) {
                int col = wn * 16 + ni * 8 + 2 * c;
                if (m0 < N) {
                    float2 v = make_float2(fmaxf(acc[mi][ni][0], 0.f), fmaxf(acc[mi][ni][1], 0.f));
                    *reinterpret_cast<float2*>(out + (size_t)m0 * 64 + col) = v;
                }
                if (m0 + 8 < N) {
                    float2 v = make_float2(fmaxf(acc[mi][ni][2], 0.f), fmaxf(acc[mi][ni][3], 0.f));
                    *reinterpret_cast<float2*>(out + (size_t)(m0 + 8) * 64 + col) = v;
                }
            }
        }
    } else {
        float lb = lp.linb[0];
        float ap = lp.pa[0];
        float pl[2] = {0.f, 0.f}, ph[2] = {0.f, 0.f};
#pragma unroll
        for (int mi = 0; mi < 2; mi++) {
#pragma unroll
            for (int ni = 0; ni < 2; ni++) {
                int col = wn * 16 + ni * 8 + 2 * c;
                float w0 = lp.linW[col], w1 = lp.linW[col + 1];
                pl[mi] += fmaxf(acc[mi][ni][0], 0.f) * w0 + fmaxf(acc[mi][ni][1], 0.f) * w1;
                ph[mi] += fmaxf(acc[mi][ni][2], 0.f) * w0 + fmaxf(acc[mi][ni][3], 0.f) * w1;
            }
            pl[mi] += __shfl_xor_sync(0xffffffffu, pl[mi], 1);
            pl[mi] += __shfl_xor_sync(0xffffffffu, pl[mi], 2);
            ph[mi] += __shfl_xor_sync(0xffffffffu, ph[mi], 1);
            ph[mi] += __shfl_xor_sync(0xffffffffu, ph[mi], 2);
        }
        if (c == 0) {
#pragma unroll
            for (int mi = 0; mi < 2; mi++) {
                sred[wn * 128 + wm * 32 + mi * 16 + r] = pl[mi];
                sred[wn * 128 + wm * 32 + mi * 16 + r + 8] = ph[mi];
            }
        }
        __syncthreads();
        if (tid < 128) {
            float v = sred[tid] + sred[128 + tid] + sred[256 + tid] + sred[384 + tid] + lb;
            int n = nbase + tid;
            if (n < N) out[n] = (v >= 0.f) ? v : ap * v;
        }
    }
}

// ---------------- launch ----------------
extern "C" void kernel_launch(void* const* d_in, const int* in_sizes, int n_in,
                              void* d_out, int out_size) {
    const float* x_pf = (const float*)d_in[0];
    const float* x_gw = (const float*)d_in[1];
    const float* x_sw = (const float*)d_in[2];
    const float* W1l  = (const float*)d_in[3];
    const float* b1l  = (const float*)d_in[4];
    const float* W1r  = (const float*)d_in[5];
    const float* W2l  = (const float*)d_in[6];
    const float* b2l  = (const float*)d_in[7];
    const float* W2r  = (const float*)d_in[8];
    const float* linW = (const float*)d_in[9];
    const float* linb = (const float*)d_in[10];
    const float* pa   = (const float*)d_in[11];
    const int* eis[7] = {
        (const int*)d_in[12],  // pf_gw
        (const int*)d_in[16],  // sw_gw
        (const int*)d_in[18],  // gw_gw
        (const int*)d_in[13],  // gw_pf
        (const int*)d_in[15],  // sw_pf
        (const int*)d_in[14],  // pf_sw
        (const int*)d_in[17],  // gw_sw
    };
    float* out = (float*)d_out;
    int E = in_sizes[12] / 2;

    float* scr;
    cudaGetSymbolAddress((void**)&scr, g_scratch);

    float* h1_pf = scr + OFF_H1;
    float* h1_gw = h1_pf + (size_t)NPF * 64;
    float* h1_sw = h1_gw + (size_t)NGW * 64;

    int* cnt_base    = (int*)(scr + OFF_CNT);
    int* fill_base   = (int*)(scr + OFF_FILL);
    int* incl        = (int*)(scr + OFF_INCL);
    int* bsums       = (int*)(scr + OFF_BSUMS);
    int* rowptr_base = (int*)(scr + OFF_ROWPTR);
    int* colidx_base = (int*)(scr + OFF_COLIDX);

    const int ns[7] = {NGW, NGW, NGW, NPF, NPF, NSW, NSW};
    ScanCfg sc;
    int cnt_pad_total = 0;
    {
        int po = 0, ro = 0;
        for (int t = 0; t < 7; t++) {
            sc.ps[t] = po;
            sc.n[t] = ns[t];
            sc.nblk[t] = (ns[t] + 1023) / 1024;
            sc.rpo[t] = ro;
            po += sc.nblk[t] * 1024;
            ro += ns[t] + 1;
        }
        cnt_pad_total = po;
    }

    Ptrs7i pei, prp;
    Ptrs7o pcnt, pfill, pcol;
    int* rps[7]; int* cols[7];
    for (int t = 0; t < 7; t++) {
        pei.p[t]  = eis[t];
        pcnt.p[t] = cnt_base + sc.ps[t];
        pfill.p[t] = fill_base + sc.ps[t];
        rps[t] = rowptr_base + sc.rpo[t];
        prp.p[t] = rps[t];
        cols[t] = colidx_base + (size_t)t * EMAX;
        pcol.p[t] = cols[t];
    }

    float* wbase  = scr + OFF_WCAT;
    float* wL1_gw = wbase;
    float* wL1_pf = wL1_gw + 8192;
    float* wL1_sw = wL1_pf + 6144;
    float* wL2_gw = wL1_sw + 6144;
    float* wL2_pf = wL2_gw + 16384;
    float* wL2_sw = wL2_pf + 12288;
    float* bL1_gw = wL2_sw + 12288;
    float* bL1_pf = bL1_gw + 64;
    float* bL1_sw = bL1_pf + 64;
    float* bL2_gw = bL1_sw + 64;
    float* bL2_pf = bL2_gw + 64;
    float* bL2_sw = bL2_pf + 64;

    // ---- CSR build ----
    cudaMemsetAsync(cnt_base, 0, (size_t)cnt_pad_total * sizeof(int), 0);
    cudaMemsetAsync(fill_base, 0, (size_t)cnt_pad_total * sizeof(int), 0);
    {
        dim3 g((E + 255) / 256, 7);
        count_all<<<g, 256>>>(pei, pcnt, E);
    }
    {
        dim3 g(300, 7);
        scan_partial<<<g, 1024>>>(cnt_base, incl, bsums, sc);
        dim3 g2(1, 7);
        scan_bsums<<<g2, 512>>>(bsums, sc);
        dim3 g3((NGW + 255) / 256, 7);
        scan_final<<<g3, 256>>>(incl, bsums, rowptr_base, sc);
    }
    {
        dim3 g((E + 255) / 256, 7);
        scatter_all<<<g, 256>>>(pei, prp, pfill, pcol, E);
    }

    // ---- weights ----
    {
        WAll wa;
        wa.c[0] = {W1l, W1r, b1l, wL1_gw, bL1_gw, 32, 3, 7, 0, 4, 6};
        wa.c[1] = {W1l, W1r, b1l, wL1_pf, bL1_pf, 32, 2, 9, 1, 3, -1};
        wa.c[2] = {W1l, W1r, b1l, wL1_sw, bL1_sw, 32, 2, 8, 2, 5, -1};
        wa.c[3] = {W2l, W2r, b2l, wL2_gw, bL2_gw, 64, 3, 7, 0, 4, 6};
        wa.c[4] = {W2l, W2r, b2l, wL2_pf, bL2_pf, 64, 2, 9, 1, 3, -1};
        wa.c[5] = {W2l, W2r, b2l, wL2_sw, bL2_sw, 64, 2, 8, 2, 5, -1};
        dim3 g(64, 6);
        build_wcat_all<<<g, 256>>>(wa);
    }

    const int BGW = (NGW + 127) / 128;   // 2344
    const int BPF = (NPF + 127) / 128;   // 469
    const int BSW = (NSW + 127) / 128;   // 469
    const int BTOT = BGW + BPF + BSW;    // 3282

    // ---- layer 1 (Din=32): one launch, 3 types ----
    {
        LayerParams lp;
        lp.linW = linW; lp.linb = linb; lp.pa = pa;
        lp.t[0] = {{rps[0], rps[1], rps[2]}, {cols[0], cols[1], cols[2]},
                   {x_pf, x_sw, x_gw}, x_gw, wL1_gw, bL1_gw, h1_gw,
                   NGW, 3, 128, 0, 0};
        lp.t[1] = {{rps[3], rps[4], rps[4]}, {cols[3], cols[4], cols[4]},
                   {x_gw, x_sw, x_sw}, x_pf, wL1_pf, bL1_pf, h1_pf,
                   NPF, 2, 96, 0, BGW};
        lp.t[2] = {{rps[5], rps[6], rps[6]}, {cols[5], cols[6], cols[6]},
                   {x_pf, x_gw, x_gw}, x_sw, wL1_sw, bL1_sw, h1_sw,
                   NSW, 2, 96, 0, BGW + BPF};
        fused_multi<32><<<BTOT, 512>>>(lp);
    }

    // ---- layer 2 (Din=64): one launch, 3 types ----
    // out layout: out_gw [NGW], out_sw [NSW], h_pf [NPF*64]
    {
        LayerParams lp;
        lp.linW = linW; lp.linb = linb; lp.pa = pa;
        lp.t[0] = {{rps[0], rps[1], rps[2]}, {cols[0], cols[1], cols[2]},
                   {h1_pf, h1_sw, h1_gw}, h1_gw, wL2_gw, bL2_gw, out,
                   NGW, 3, 256, 1, 0};
        lp.t[1] = {{rps[3], rps[4], rps[4]}, {cols[3], cols[4], cols[4]},
                   {h1_gw, h1_sw, h1_sw}, h1_pf, wL2_pf, bL2_pf, out + NGW + NSW,
                   NPF, 2, 192, 0, BGW};
        lp.t[2] = {{rps[5], rps[6], rps[6]}, {cols[5], cols[6], cols[6]},
                   {h1_pf, h1_gw, h1_gw}, h1_sw, wL2_sw, bL2_sw, out + NGW,
                   NSW, 2, 192, 1, BGW + BPF};
        fused_multi<64><<<BTOT, 512>>>(lp);
    }
}